// round 7
// baseline (speedup 1.0000x reference)
#include <cuda_runtime.h>
#include <cuda_bf16.h>
#include <cstdint>

// ======================= problem constants =======================
// B=4096, D=512, rows = 2B = 8192. sim = F F^T / 0.1. Fixed shift C = 10
// (cosine <= 1 exactly) removes the softmax max pass entirely.
#define NROWS 8192
#define NDIM  512
#define NB    4096
// exp(10*(d-1)) = 2^( (d-1)*10*log2(e) )
#define EX2_SCALE 14.4269504089f

// ======================= device scratch (no allocs allowed) =====
static __device__ __align__(16) __nv_bfloat16 g_F[NROWS * NDIM];  // 8 MB normalized bf16
static __device__ float g_pos[NB];                                 // exact fp32 pos-pair sim/T
static __device__ float g_partial[64 * 2 * 128];                   // [rowtile][half][row]

// ======================= PTX helpers (non-'a' features only) =====
__device__ __forceinline__ uint32_t smem_u32(const void* p) {
    uint32_t a;
    asm("{ .reg .u64 t; cvta.to.shared.u64 t, %1; cvt.u32.u64 %0, t; }" : "=r"(a) : "l"(p));
    return a;
}
__device__ __forceinline__ void cp16(uint32_t saddr, const void* g) {
    asm volatile("cp.async.cg.shared.global [%0], [%1], 16;" :: "r"(saddr), "l"(g));
}
__device__ __forceinline__ void cp_commit() { asm volatile("cp.async.commit_group;" ::: "memory"); }
template <int N>
__device__ __forceinline__ void cp_wait() { asm volatile("cp.async.wait_group %0;" :: "n"(N) : "memory"); }

__device__ __forceinline__ void ldsm_x4(uint32_t& r0, uint32_t& r1, uint32_t& r2, uint32_t& r3,
                                        uint32_t addr) {
    asm volatile("ldmatrix.sync.aligned.m8n8.x4.shared.b16 {%0,%1,%2,%3}, [%4];"
                 : "=r"(r0), "=r"(r1), "=r"(r2), "=r"(r3)
                 : "r"(addr));
}
__device__ __forceinline__ void mma16816(float* d, uint32_t a0, uint32_t a1, uint32_t a2,
                                         uint32_t a3, uint32_t b0, uint32_t b1) {
    asm volatile(
        "mma.sync.aligned.m16n8k16.row.col.f32.bf16.bf16.f32 "
        "{%0,%1,%2,%3}, {%4,%5,%6,%7}, {%8,%9}, {%0,%1,%2,%3};"
        : "+f"(d[0]), "+f"(d[1]), "+f"(d[2]), "+f"(d[3])
        : "r"(a0), "r"(a1), "r"(a2), "r"(a3), "r"(b0), "r"(b1));
}

// ======================= kernel A: normalize -> bf16 =============
__global__ void k_normalize(const float* __restrict__ f1, const float* __restrict__ f2) {
    int row = blockIdx.x;  // 0..8191
    const float* src = (row < NB) ? (f1 + (size_t)row * NDIM)
                                  : (f2 + (size_t)(row - NB) * NDIM);
    int tid = threadIdx.x;  // 128
    float v[4];
    float ss = 0.f;
#pragma unroll
    for (int i = 0; i < 4; i++) {
        v[i] = src[tid + i * 128];
        ss += v[i] * v[i];
    }
#pragma unroll
    for (int o = 16; o > 0; o >>= 1) ss += __shfl_xor_sync(0xFFFFFFFFu, ss, o);
    __shared__ float sred[4];
    if ((tid & 31) == 0) sred[tid >> 5] = ss;
    __syncthreads();
    float tot = sred[0] + sred[1] + sred[2] + sred[3];
    float scale = 1.f / fmaxf(sqrtf(tot), 1e-12f);
#pragma unroll
    for (int i = 0; i < 4; i++)
        g_F[(size_t)row * NDIM + tid + i * 128] = __float2bfloat16(v[i] * scale);
}

// ======================= kernel B: exact positive-pair sims ======
__global__ void k_pos(const float* __restrict__ f1, const float* __restrict__ f2) {
    int i = blockIdx.x;  // 0..4095
    int tid = threadIdx.x;  // 128
    const float* a = f1 + (size_t)i * NDIM;
    const float* b = f2 + (size_t)i * NDIM;
    float s11 = 0.f, s22 = 0.f, s12 = 0.f;
#pragma unroll
    for (int c = tid; c < NDIM; c += 128) {
        float x = a[c], y = b[c];
        s11 += x * x; s22 += y * y; s12 += x * y;
    }
#pragma unroll
    for (int o = 16; o > 0; o >>= 1) {
        s11 += __shfl_xor_sync(0xFFFFFFFFu, s11, o);
        s22 += __shfl_xor_sync(0xFFFFFFFFu, s22, o);
        s12 += __shfl_xor_sync(0xFFFFFFFFu, s12, o);
    }
    __shared__ float r11[4], r22[4], r12[4];
    if ((tid & 31) == 0) { r11[tid >> 5] = s11; r22[tid >> 5] = s22; r12[tid >> 5] = s12; }
    __syncthreads();
    if (tid == 0) {
        float t11 = r11[0] + r11[1] + r11[2] + r11[3];
        float t22 = r22[0] + r22[1] + r22[2] + r22[3];
        float t12 = r12[0] + r12[1] + r12[2] + r12[3];
        float inv1 = 1.f / fmaxf(sqrtf(t11), 1e-12f);
        float inv2 = 1.f / fmaxf(sqrtf(t22), 1e-12f);
        g_pos[i] = t12 * inv1 * inv2 * 10.f;  // sim/T
    }
}

// ======================= kernel C: fused GEMM + exp-sum ==========
// mma.sync (HMMA) path: compute_103 target has no tcgen05.
// Grid: 128 CTAs = 64 row-tiles (M=128) x 2 column halves (4096 cols each).
// 256 threads = 8 warps in a 4(M) x 2(N) grid; warp tile 32x64.
// A (128x512 bf16) resident in SMEM, pitch 520 elems (1040B: +16B pad =>
// conflict-free ldmatrix). B streamed in 128(n) x 128(k) chunks, double-
// buffered via cp.async; next tile's first chunk prefetched across the
// epilogue.
static constexpr int A_PITCH_B = 1040;                    // bytes per A row
static constexpr int B_PITCH_B = 272;                     // bytes per B row
static constexpr int A_BYTES = 128 * A_PITCH_B;           // 133120
static constexpr int B_BUF_BYTES = 128 * B_PITCH_B;       // 34816
static constexpr int SMEM_DYN = A_BYTES + 2 * B_BUF_BYTES;  // 202752

__device__ __forceinline__ void issue_B(uint32_t b_buf_base, int tid, int n0, int kc) {
#pragma unroll
    for (int i = 0; i < 8; i++) {
        int u = tid + i * 256;
        int row = u >> 4, g = u & 15;
        cp16(b_buf_base + row * B_PITCH_B + g * 16,
             &g_F[(size_t)(n0 + row) * NDIM + kc * 128 + g * 8]);
    }
    cp_commit();
}

__global__ __launch_bounds__(256, 1) void k_infonce() {
    extern __shared__ char dyn[];
    uint32_t A_base = smem_u32(dyn);
    uint32_t B_base = A_base + A_BYTES;
    __shared__ float srow[128];

    int tid = threadIdx.x;
    int wid = tid >> 5, lane = tid & 31;
    int warpm = wid >> 1, warpn = wid & 1;  // 4 x 2
    int bid = blockIdx.x;
    int rowtile = bid >> 1, half = bid & 1;
    int m0 = rowtile * 128;
    int nbase = half * 4096;

    if (tid < 128) srow[tid] = 0.f;

    // Load A: 128 rows x 512 cols = 8192 uint4 (64 groups/row), pitch 1040B.
    // (Round-5 bug: only 32 groups/row were loaded -> NaN from uninit SMEM.)
    {
        char* A_ptr = dyn;
#pragma unroll
        for (int i = 0; i < 32; i++) {
            int u = tid + i * 256;
            int row = u >> 6, g = u & 63;
            uint4 v = *reinterpret_cast<const uint4*>(&g_F[(size_t)(m0 + row) * NDIM + g * 8]);
            *reinterpret_cast<uint4*>(A_ptr + row * A_PITCH_B + g * 16) = v;
        }
    }
    __syncthreads();

    // ldmatrix per-lane address components (same group layout for A and B):
    // lanes [0..7]: rows +0, k-lo; [8..15]: rows +8, k-lo; [16..23]: rows +0, k-hi;
    // [24..31]: rows +8, k-hi.
    int rowadd = ((lane >> 3) & 1) * 8 + (lane & 7);
    int kadd = (lane >> 4) * 16;

    uint32_t aAddr[2];
#pragma unroll
    for (int mf = 0; mf < 2; mf++)
        aAddr[mf] = A_base + (warpm * 32 + mf * 16 + rowadd) * A_PITCH_B + kadd;
    uint32_t bAddrRel[4];
#pragma unroll
    for (int nf = 0; nf < 4; nf++)
        bAddrRel[nf] = (warpn * 64 + nf * 16 + rowadd) * B_PITCH_B + kadd;

    float accRow[4] = {0.f, 0.f, 0.f, 0.f};
    int grBase = m0 + warpm * 32 + (lane >> 2);  // rows grBase + {0,8,16,24}

    // Prefetch first B chunk of first tile.
    issue_B(B_base, tid, nbase, 0);

    for (int t = 0; t < 32; ++t) {
        int n0 = nbase + t * 128;
        float acc[2][8][4];
#pragma unroll
        for (int mf = 0; mf < 2; mf++)
#pragma unroll
            for (int q = 0; q < 8; q++)
#pragma unroll
                for (int j = 0; j < 4; j++) acc[mf][q][j] = 0.f;

        for (int kc = 0; kc < 4; ++kc) {
            bool issued;
            if (kc < 3) {
                issue_B(B_base + ((kc + 1) & 1) * B_BUF_BYTES, tid, n0, kc + 1);
                issued = true;
            } else if (t < 31) {
                issue_B(B_base, tid, n0 + 128, 0);  // next tile chunk 0 -> buf0
                issued = true;
            } else {
                issued = false;
            }
            if (issued) cp_wait<1>(); else cp_wait<0>();
            __syncthreads();

            uint32_t bBuf = B_base + (kc & 1) * B_BUF_BYTES;
#pragma unroll
            for (int ks = 0; ks < 8; ++ks) {
                uint32_t a[2][4];
#pragma unroll
                for (int mf = 0; mf < 2; mf++)
                    ldsm_x4(a[mf][0], a[mf][1], a[mf][2], a[mf][3],
                            aAddr[mf] + kc * 256 + ks * 32);
#pragma unroll
                for (int nf = 0; nf < 4; nf++) {
                    uint32_t b0, b1, b2, b3;  // {n-lo k-lo, n-hi k-lo, n-lo k-hi, n-hi k-hi}
                    ldsm_x4(b0, b1, b2, b3, bBuf + bAddrRel[nf] + ks * 32);
#pragma unroll
                    for (int mf = 0; mf < 2; mf++) {
                        mma16816(acc[mf][nf * 2 + 0], a[mf][0], a[mf][1], a[mf][2], a[mf][3],
                                 b0, b2);
                        mma16816(acc[mf][nf * 2 + 1], a[mf][0], a[mf][1], a[mf][2], a[mf][3],
                                 b1, b3);
                    }
                }
            }
            __syncthreads();  // all warps done reading this buffer before reuse
        }

        // Epilogue: exp(10*(d-1)) accumulated per owned row; diagonal skipped.
#pragma unroll
        for (int mf = 0; mf < 2; mf++) {
            int gr0 = grBase + mf * 16;
#pragma unroll
            for (int q = 0; q < 8; q++) {
                int c0 = n0 + warpn * 64 + (q >> 1) * 16 + (q & 1) * 8 + 2 * (lane & 3);
#pragma unroll
                for (int j = 0; j < 4; j++) {
                    float arg = fmaf(acc[mf][q][j], EX2_SCALE, -EX2_SCALE);
                    float e;
                    asm("ex2.approx.ftz.f32 %0, %1;" : "=f"(e) : "f"(arg));
                    int gc = c0 + (j & 1);
                    int gr = gr0 + (j >> 1) * 8;
                    if (gc != gr) accRow[mf * 2 + (j >> 1)] += e;
                }
            }
        }
    }

    // Reduce per-thread row partials into srow, then to global.
    __syncthreads();
#pragma unroll
    for (int i = 0; i < 4; i++) {
        float v = accRow[i];
        v += __shfl_xor_sync(0xFFFFFFFFu, v, 1);
        v += __shfl_xor_sync(0xFFFFFFFFu, v, 2);
        if ((lane & 3) == 0)
            atomicAdd(&srow[warpm * 32 + i * 8 + (lane >> 2)], v);
    }
    __syncthreads();
    if (tid < 128)
        g_partial[(rowtile * 2 + half) * 128 + tid] = srow[tid];
}

// ======================= kernel D: final reduction ===============
__global__ void k_finish(float* __restrict__ out) {
    int tid = threadIdx.x;  // 256
    float acc = 0.f;
    for (int r = tid; r < NROWS; r += 256) {
        int rt = r >> 7, ri = r & 127;
        float l = g_partial[(rt * 2 + 0) * 128 + ri] + g_partial[(rt * 2 + 1) * 128 + ri];
        // LSE_r = 10 + log(sum exp(sim-10));  loss_r = LSE_r - pos-pair sim
        acc += 10.f + logf(l) - g_pos[r & (NB - 1)];
    }
#pragma unroll
    for (int o = 16; o > 0; o >>= 1) acc += __shfl_xor_sync(0xFFFFFFFFu, acc, o);
    __shared__ float sred[8];
    if ((tid & 31) == 0) sred[tid >> 5] = acc;
    __syncthreads();
    if (tid == 0) {
        float t = 0.f;
#pragma unroll
        for (int i = 0; i < 8; i++) t += sred[i];
        out[0] = t / (float)NROWS;
    }
}

// ======================= launch ==================================
extern "C" void kernel_launch(void* const* d_in, const int* in_sizes, int n_in,
                              void* d_out, int out_size) {
    const float* f1 = (const float*)d_in[0];
    const float* f2 = (const float*)d_in[1];
    float* out = (float*)d_out;

    cudaFuncSetAttribute(k_infonce, cudaFuncAttributeMaxDynamicSharedMemorySize, SMEM_DYN);

    k_normalize<<<NROWS, 128>>>(f1, f2);
    k_pos<<<NB, 128>>>(f1, f2);
    k_infonce<<<128, 256, SMEM_DYN>>>();
    k_finish<<<1, 256>>>(out);
}

// round 8
// speedup vs baseline: 1.6477x; 1.6477x over previous
#include <cuda_runtime.h>
#include <cuda_bf16.h>
#include <cstdint>

// ======================= problem constants =======================
// B=4096, D=512, rows = 2B = 8192. sim = F F^T / 0.1. Fixed shift C = 10
// (cosine <= 1 exactly) removes the softmax max pass entirely.
// Symmetry: exp(sim-10) is symmetric -> each off-diagonal 128x128 tile is
// computed once and contributes to row partials (tile i) AND col partials
// (tile j). 2080 tiles instead of 4096.
#define NROWS 8192
#define NDIM  512
#define NB    4096
#define EX2_SCALE 14.4269504089f

// ======================= device scratch (no allocs allowed) =====
static __device__ __align__(16) __nv_bfloat16 g_F[NROWS * NDIM];  // 8 MB normalized bf16
static __device__ float g_pos[NB];      // exact fp32 pos-pair sim/T
static __device__ float g_rowsum[NROWS];  // sum_c!=r exp(sim-10), atomically accumulated

// ======================= PTX helpers (non-'a' features only) =====
__device__ __forceinline__ uint32_t smem_u32(const void* p) {
    uint32_t a;
    asm("{ .reg .u64 t; cvta.to.shared.u64 t, %1; cvt.u32.u64 %0, t; }" : "=r"(a) : "l"(p));
    return a;
}
__device__ __forceinline__ void cp16(uint32_t saddr, const void* g) {
    asm volatile("cp.async.cg.shared.global [%0], [%1], 16;" :: "r"(saddr), "l"(g));
}
__device__ __forceinline__ void cp_commit() { asm volatile("cp.async.commit_group;" ::: "memory"); }
template <int N>
__device__ __forceinline__ void cp_wait() { asm volatile("cp.async.wait_group %0;" :: "n"(N) : "memory"); }

__device__ __forceinline__ void ldsm_x4(uint32_t& r0, uint32_t& r1, uint32_t& r2, uint32_t& r3,
                                        uint32_t addr) {
    asm volatile("ldmatrix.sync.aligned.m8n8.x4.shared.b16 {%0,%1,%2,%3}, [%4];"
                 : "=r"(r0), "=r"(r1), "=r"(r2), "=r"(r3)
                 : "r"(addr));
}
__device__ __forceinline__ void mma16816(float* d, uint32_t a0, uint32_t a1, uint32_t a2,
                                         uint32_t a3, uint32_t b0, uint32_t b1) {
    asm volatile(
        "mma.sync.aligned.m16n8k16.row.col.f32.bf16.bf16.f32 "
        "{%0,%1,%2,%3}, {%4,%5,%6,%7}, {%8,%9}, {%0,%1,%2,%3};"
        : "+f"(d[0]), "+f"(d[1]), "+f"(d[2]), "+f"(d[3])
        : "r"(a0), "r"(a1), "r"(a2), "r"(a3), "r"(b0), "r"(b1));
}

// ======================= kernel Z: zero accumulators =============
__global__ void k_zero(float* __restrict__ out) {
    int idx = blockIdx.x * 256 + threadIdx.x;
    if (idx < NROWS) g_rowsum[idx] = 0.f;
    if (idx == 0) out[0] = 0.f;
}

// ======================= kernel A: normalize -> bf16 =============
__global__ void k_normalize(const float* __restrict__ f1, const float* __restrict__ f2) {
    int row = blockIdx.x;  // 0..8191
    const float* src = (row < NB) ? (f1 + (size_t)row * NDIM)
                                  : (f2 + (size_t)(row - NB) * NDIM);
    int tid = threadIdx.x;  // 128
    float v[4];
    float ss = 0.f;
#pragma unroll
    for (int i = 0; i < 4; i++) {
        v[i] = src[tid + i * 128];
        ss += v[i] * v[i];
    }
#pragma unroll
    for (int o = 16; o > 0; o >>= 1) ss += __shfl_xor_sync(0xFFFFFFFFu, ss, o);
    __shared__ float sred[4];
    if ((tid & 31) == 0) sred[tid >> 5] = ss;
    __syncthreads();
    float tot = sred[0] + sred[1] + sred[2] + sred[3];
    float scale = 1.f / fmaxf(sqrtf(tot), 1e-12f);
#pragma unroll
    for (int i = 0; i < 4; i++)
        g_F[(size_t)row * NDIM + tid + i * 128] = __float2bfloat16(v[i] * scale);
}

// ======================= kernel B: exact positive-pair sims ======
__global__ void k_pos(const float* __restrict__ f1, const float* __restrict__ f2) {
    int i = blockIdx.x;  // 0..4095
    int tid = threadIdx.x;  // 128
    const float* a = f1 + (size_t)i * NDIM;
    const float* b = f2 + (size_t)i * NDIM;
    float s11 = 0.f, s22 = 0.f, s12 = 0.f;
#pragma unroll
    for (int c = tid; c < NDIM; c += 128) {
        float x = a[c], y = b[c];
        s11 += x * x; s22 += y * y; s12 += x * y;
    }
#pragma unroll
    for (int o = 16; o > 0; o >>= 1) {
        s11 += __shfl_xor_sync(0xFFFFFFFFu, s11, o);
        s22 += __shfl_xor_sync(0xFFFFFFFFu, s22, o);
        s12 += __shfl_xor_sync(0xFFFFFFFFu, s12, o);
    }
    __shared__ float r11[4], r22[4], r12[4];
    if ((tid & 31) == 0) { r11[tid >> 5] = s11; r22[tid >> 5] = s22; r12[tid >> 5] = s12; }
    __syncthreads();
    if (tid == 0) {
        float t11 = r11[0] + r11[1] + r11[2] + r11[3];
        float t22 = r22[0] + r22[1] + r22[2] + r22[3];
        float t12 = r12[0] + r12[1] + r12[2] + r12[3];
        float inv1 = 1.f / fmaxf(sqrtf(t11), 1e-12f);
        float inv2 = 1.f / fmaxf(sqrtf(t22), 1e-12f);
        g_pos[i] = t12 * inv1 * inv2 * 10.f;  // sim/T
    }
}

// ======================= kernel C: symmetric fused GEMM + exp-sum
// Grid: 128 CTAs = 64 row-tiles x 2 parity splits. CTA (i, p) handles
// forward-distance tiles t = p, p+2, ... < T_i, where T_i = 33 for i<32
// else 32 (each unordered tile pair covered exactly once).
// Per tile j=(i+t)%64: D = A_i B_j^T (128x128), epilogue adds exp(10(d-1))
// to row partials of tile i, and (t>0) column partials of tile j via
// butterfly reduce + global atomics. t==0: diagonal masked, rows only.
static constexpr int A_PITCH_B = 1040;                    // bytes per A row
static constexpr int B_PITCH_B = 272;                     // bytes per B row
static constexpr int A_BYTES = 128 * A_PITCH_B;           // 133120
static constexpr int B_BUF_BYTES = 128 * B_PITCH_B;       // 34816
static constexpr int SMEM_DYN = A_BYTES + 2 * B_BUF_BYTES;  // 202752

__device__ __forceinline__ void issue_B(uint32_t b_buf_base, int tid, int n0, int kc) {
#pragma unroll
    for (int i = 0; i < 8; i++) {
        int u = tid + i * 256;
        int row = u >> 4, g = u & 15;
        cp16(b_buf_base + row * B_PITCH_B + g * 16,
             &g_F[(size_t)(n0 + row) * NDIM + kc * 128 + g * 8]);
    }
    cp_commit();
}

__global__ __launch_bounds__(256, 1) void k_infonce() {
    extern __shared__ char dyn[];
    uint32_t A_base = smem_u32(dyn);
    uint32_t B_base = A_base + A_BYTES;
    __shared__ float srow[128];

    int tid = threadIdx.x;
    int wid = tid >> 5, lane = tid & 31;
    int warpm = wid >> 1, warpn = wid & 1;  // 4 x 2
    int bid = blockIdx.x;
    int rowtile = bid >> 1, par = bid & 1;
    int m0 = rowtile * 128;
    int T = (rowtile < 32) ? 33 : 32;

    if (tid < 128) srow[tid] = 0.f;

    // Load A: 128 rows x 512 cols = 8192 uint4 (64 groups/row), pitch 1040B.
    {
        char* A_ptr = dyn;
#pragma unroll
        for (int i = 0; i < 32; i++) {
            int u = tid + i * 256;
            int row = u >> 6, g = u & 63;
            uint4 v = *reinterpret_cast<const uint4*>(&g_F[(size_t)(m0 + row) * NDIM + g * 8]);
            *reinterpret_cast<uint4*>(A_ptr + row * A_PITCH_B + g * 16) = v;
        }
    }
    __syncthreads();

    // ldmatrix per-lane address components.
    int rowadd = ((lane >> 3) & 1) * 8 + (lane & 7);
    int kadd = (lane >> 4) * 16;

    uint32_t aAddr[2];
#pragma unroll
    for (int mf = 0; mf < 2; mf++)
        aAddr[mf] = A_base + (warpm * 32 + mf * 16 + rowadd) * A_PITCH_B + kadd;
    uint32_t bAddrRel[4];
#pragma unroll
    for (int nf = 0; nf < 4; nf++)
        bAddrRel[nf] = (warpn * 64 + nf * 16 + rowadd) * B_PITCH_B + kadd;

    float accRow[4] = {0.f, 0.f, 0.f, 0.f};
    int grBase = m0 + warpm * 32 + (lane >> 2);  // rows grBase + {0,8,16,24}

    // Prefetch first tile's chunk 0.
    issue_B(B_base, tid, ((rowtile + par) & 63) * 128, 0);

    for (int t = par; t < T; t += 2) {
        int n0 = ((rowtile + t) & 63) * 128;
        float acc[2][8][4];
#pragma unroll
        for (int mf = 0; mf < 2; mf++)
#pragma unroll
            for (int q = 0; q < 8; q++)
#pragma unroll
                for (int j = 0; j < 4; j++) acc[mf][q][j] = 0.f;

        for (int kc = 0; kc < 4; ++kc) {
            bool issued;
            if (kc < 3) {
                issue_B(B_base + ((kc + 1) & 1) * B_BUF_BYTES, tid, n0, kc + 1);
                issued = true;
            } else if (t + 2 < T) {
                issue_B(B_base, tid, ((rowtile + t + 2) & 63) * 128, 0);
                issued = true;
            } else {
                issued = false;
            }
            if (issued) cp_wait<1>(); else cp_wait<0>();
            __syncthreads();

            uint32_t bBuf = B_base + (kc & 1) * B_BUF_BYTES;
#pragma unroll
            for (int ks = 0; ks < 8; ++ks) {
                uint32_t a[2][4];
#pragma unroll
                for (int mf = 0; mf < 2; mf++)
                    ldsm_x4(a[mf][0], a[mf][1], a[mf][2], a[mf][3],
                            aAddr[mf] + kc * 256 + ks * 32);
#pragma unroll
                for (int nf = 0; nf < 4; nf++) {
                    uint32_t b0, b1, b2, b3;
                    ldsm_x4(b0, b1, b2, b3, bBuf + bAddrRel[nf] + ks * 32);
#pragma unroll
                    for (int mf = 0; mf < 2; mf++) {
                        mma16816(acc[mf][nf * 2 + 0], a[mf][0], a[mf][1], a[mf][2], a[mf][3],
                                 b0, b2);
                        mma16816(acc[mf][nf * 2 + 1], a[mf][0], a[mf][1], a[mf][2], a[mf][3],
                                 b1, b3);
                    }
                }
            }
            __syncthreads();  // all warps done reading this buffer before reuse
        }

        // ---------------- epilogue ----------------
        if (t == 0) {
            // Diagonal tile: row sums only, self-similarity masked.
#pragma unroll
            for (int mf = 0; mf < 2; mf++) {
                int gr0 = grBase + mf * 16;
#pragma unroll
                for (int q = 0; q < 8; q++) {
                    int c0 = n0 + warpn * 64 + (q >> 1) * 16 + (q & 1) * 8 + 2 * (lane & 3);
#pragma unroll
                    for (int j = 0; j < 4; j++) {
                        float arg = fmaf(acc[mf][q][j], EX2_SCALE, -EX2_SCALE);
                        float e;
                        asm("ex2.approx.ftz.f32 %0, %1;" : "=f"(e) : "f"(arg));
                        int gc = c0 + (j & 1);
                        int gr = gr0 + (j >> 1) * 8;
                        if (gc != gr) accRow[mf * 2 + (j >> 1)] += e;
                    }
                }
            }
        } else {
            // Off-diagonal tile: rows (tile i) + columns (tile j).
            float colAcc[16];
#pragma unroll
            for (int x = 0; x < 16; x++) colAcc[x] = 0.f;
#pragma unroll
            for (int mf = 0; mf < 2; mf++) {
#pragma unroll
                for (int q = 0; q < 8; q++) {
#pragma unroll
                    for (int j = 0; j < 4; j++) {
                        float arg = fmaf(acc[mf][q][j], EX2_SCALE, -EX2_SCALE);
                        float e;
                        asm("ex2.approx.ftz.f32 %0, %1;" : "=f"(e) : "f"(arg));
                        accRow[mf * 2 + (j >> 1)] += e;
                        colAcc[q * 2 + (j & 1)] += e;
                    }
                }
            }
            // Butterfly-reduce col sums over the 8 lanes sharing lane&3,
            // then 4 lanes issue spread global atomics (16 cols/warp).
#pragma unroll
            for (int x = 0; x < 16; x++) {
                float v = colAcc[x];
                v += __shfl_xor_sync(0xFFFFFFFFu, v, 4);
                v += __shfl_xor_sync(0xFFFFFFFFu, v, 8);
                v += __shfl_xor_sync(0xFFFFFFFFu, v, 16);
                if (lane < 4) {
                    int q = x >> 1, jlo = x & 1;
                    int col = n0 + warpn * 64 + (q >> 1) * 16 + (q & 1) * 8 + 2 * lane + jlo;
                    atomicAdd(&g_rowsum[col], v);
                }
            }
        }
    }

    // Row partials: reduce into srow, then atomically to global.
    __syncthreads();
#pragma unroll
    for (int i = 0; i < 4; i++) {
        float v = accRow[i];
        v += __shfl_xor_sync(0xFFFFFFFFu, v, 1);
        v += __shfl_xor_sync(0xFFFFFFFFu, v, 2);
        if ((lane & 3) == 0)
            atomicAdd(&srow[warpm * 32 + i * 8 + (lane >> 2)], v);
    }
    __syncthreads();
    if (tid < 128)
        atomicAdd(&g_rowsum[m0 + tid], srow[tid]);
}

// ======================= kernel D: final reduction ===============
__global__ void k_finish(float* __restrict__ out) {
    int tid = threadIdx.x;  // 256, grid 32
    int r = blockIdx.x * 256 + tid;
    // LSE_r = 10 + log(sum exp(sim-10));  loss_r = LSE_r - pos-pair sim
    float acc = 10.f + __logf(g_rowsum[r]) - g_pos[r & (NB - 1)];
#pragma unroll
    for (int o = 16; o > 0; o >>= 1) acc += __shfl_xor_sync(0xFFFFFFFFu, acc, o);
    __shared__ float sred[8];
    if ((tid & 31) == 0) sred[tid >> 5] = acc;
    __syncthreads();
    if (tid == 0) {
        float s = 0.f;
#pragma unroll
        for (int i = 0; i < 8; i++) s += sred[i];
        atomicAdd(out, s * (1.f / (float)NROWS));
    }
}

// ======================= launch ==================================
extern "C" void kernel_launch(void* const* d_in, const int* in_sizes, int n_in,
                              void* d_out, int out_size) {
    const float* f1 = (const float*)d_in[0];
    const float* f2 = (const float*)d_in[1];
    float* out = (float*)d_out;

    cudaFuncSetAttribute(k_infonce, cudaFuncAttributeMaxDynamicSharedMemorySize, SMEM_DYN);

    k_zero<<<32, 256>>>(out);
    k_normalize<<<NROWS, 128>>>(f1, f2);
    k_pos<<<NB, 128>>>(f1, f2);
    k_infonce<<<128, 256, SMEM_DYN>>>();
    k_finish<<<32, 256>>>(out);
}

// round 9
// speedup vs baseline: 1.7764x; 1.0781x over previous
#include <cuda_runtime.h>
#include <cuda_bf16.h>
#include <cstdint>

// ======================= problem constants =======================
// B=4096, D=512, rows = 2B = 8192. sim = F F^T / 0.1. Fixed shift C = 10
// (cosine <= 1 exactly) removes the softmax max pass entirely.
// Symmetry: exp(sim-10) is symmetric -> each off-diagonal 128x128 tile is
// computed once and contributes to row partials (tile i) AND col partials
// (tile j). 2080 tiles instead of 4096.
#define NROWS 8192
#define NDIM  512
#define NB    4096
#define EX2_SCALE 14.4269504089f

// ======================= device scratch (no allocs allowed) =====
static __device__ __align__(16) __nv_bfloat16 g_F[NROWS * NDIM];  // 8 MB normalized bf16
static __device__ float g_pos[NB];        // exact fp32 pos-pair sim/T
static __device__ float g_rowsum[NROWS];  // sum_c!=r exp(sim-10), atomically accumulated

// ======================= PTX helpers (non-'a' features only) =====
__device__ __forceinline__ uint32_t smem_u32(const void* p) {
    uint32_t a;
    asm("{ .reg .u64 t; cvta.to.shared.u64 t, %1; cvt.u32.u64 %0, t; }" : "=r"(a) : "l"(p));
    return a;
}
__device__ __forceinline__ void cp16(uint32_t saddr, const void* g) {
    asm volatile("cp.async.cg.shared.global [%0], [%1], 16;" :: "r"(saddr), "l"(g));
}
__device__ __forceinline__ void cp_commit() { asm volatile("cp.async.commit_group;" ::: "memory"); }
template <int N>
__device__ __forceinline__ void cp_wait() { asm volatile("cp.async.wait_group %0;" :: "n"(N) : "memory"); }

__device__ __forceinline__ void ldsm_x4(uint32_t& r0, uint32_t& r1, uint32_t& r2, uint32_t& r3,
                                        uint32_t addr) {
    asm volatile("ldmatrix.sync.aligned.m8n8.x4.shared.b16 {%0,%1,%2,%3}, [%4];"
                 : "=r"(r0), "=r"(r1), "=r"(r2), "=r"(r3)
                 : "r"(addr));
}
__device__ __forceinline__ void mma16816(float* d, uint32_t a0, uint32_t a1, uint32_t a2,
                                         uint32_t a3, uint32_t b0, uint32_t b1) {
    asm volatile(
        "mma.sync.aligned.m16n8k16.row.col.f32.bf16.bf16.f32 "
        "{%0,%1,%2,%3}, {%4,%5,%6,%7}, {%8,%9}, {%0,%1,%2,%3};"
        : "+f"(d[0]), "+f"(d[1]), "+f"(d[2]), "+f"(d[3])
        : "r"(a0), "r"(a1), "r"(a2), "r"(a3), "r"(b0), "r"(b1));
}

// ======================= kernel Z: zero accumulators =============
__global__ void k_zero(float* __restrict__ out) {
    int idx = blockIdx.x * 256 + threadIdx.x;
    if (idx < NROWS) g_rowsum[idx] = 0.f;
    if (idx == 0) out[0] = 0.f;
}

// ======================= kernel A: normalize -> bf16 =============
__global__ void k_normalize(const float* __restrict__ f1, const float* __restrict__ f2) {
    int row = blockIdx.x;  // 0..8191
    const float* src = (row < NB) ? (f1 + (size_t)row * NDIM)
                                  : (f2 + (size_t)(row - NB) * NDIM);
    int tid = threadIdx.x;  // 128
    float v[4];
    float ss = 0.f;
#pragma unroll
    for (int i = 0; i < 4; i++) {
        v[i] = src[tid + i * 128];
        ss += v[i] * v[i];
    }
#pragma unroll
    for (int o = 16; o > 0; o >>= 1) ss += __shfl_xor_sync(0xFFFFFFFFu, ss, o);
    __shared__ float sred[4];
    if ((tid & 31) == 0) sred[tid >> 5] = ss;
    __syncthreads();
    float tot = sred[0] + sred[1] + sred[2] + sred[3];
    float scale = 1.f / fmaxf(sqrtf(tot), 1e-12f);
#pragma unroll
    for (int i = 0; i < 4; i++)
        g_F[(size_t)row * NDIM + tid + i * 128] = __float2bfloat16(v[i] * scale);
}

// ======================= kernel B: exact positive-pair sims ======
__global__ void k_pos(const float* __restrict__ f1, const float* __restrict__ f2) {
    int i = blockIdx.x;  // 0..4095
    int tid = threadIdx.x;  // 128
    const float* a = f1 + (size_t)i * NDIM;
    const float* b = f2 + (size_t)i * NDIM;
    float s11 = 0.f, s22 = 0.f, s12 = 0.f;
#pragma unroll
    for (int c = tid; c < NDIM; c += 128) {
        float x = a[c], y = b[c];
        s11 += x * x; s22 += y * y; s12 += x * y;
    }
#pragma unroll
    for (int o = 16; o > 0; o >>= 1) {
        s11 += __shfl_xor_sync(0xFFFFFFFFu, s11, o);
        s22 += __shfl_xor_sync(0xFFFFFFFFu, s22, o);
        s12 += __shfl_xor_sync(0xFFFFFFFFu, s12, o);
    }
    __shared__ float r11[4], r22[4], r12[4];
    if ((tid & 31) == 0) { r11[tid >> 5] = s11; r22[tid >> 5] = s22; r12[tid >> 5] = s12; }
    __syncthreads();
    if (tid == 0) {
        float t11 = r11[0] + r11[1] + r11[2] + r11[3];
        float t22 = r22[0] + r22[1] + r22[2] + r22[3];
        float t12 = r12[0] + r12[1] + r12[2] + r12[3];
        float inv1 = 1.f / fmaxf(sqrtf(t11), 1e-12f);
        float inv2 = 1.f / fmaxf(sqrtf(t22), 1e-12f);
        g_pos[i] = t12 * inv1 * inv2 * 10.f;  // sim/T
    }
}

// ======================= kernel C: symmetric fused GEMM + exp-sum
// 128 CTAs = 64 row-tiles x 2 parity splits; CTA (i,p) handles forward
// distances t = p, p+2, ... < T_i (T_i = 33 for i<32 else 32).
// SMEM: A 128x512 bf16, pitch 1024B XOR-swizzled (128 KB); B 3-deep ring
// of 128x128 chunks, pitch 256B swizzled (96 KB). Continuous chunk stream
// across tiles: 1 cp_wait + 1 syncthreads per chunk, prefetch distance 2.
static constexpr int A_PITCH_B = 1024;
static constexpr int B_PITCH_B = 256;
static constexpr int A_BYTES = 128 * A_PITCH_B;          // 131072
static constexpr int B_BUF_BYTES = 128 * B_PITCH_B;      // 32768
static constexpr int SMEM_DYN = A_BYTES + 3 * B_BUF_BYTES;  // 229376

// swizzle: XOR 16B-group index with (row & 7)
__device__ __forceinline__ uint32_t swz(uint32_t row, uint32_t byteoff) {
    return byteoff ^ ((row & 7) << 4);
}

__device__ __forceinline__ void issue_chunk(uint32_t B_base, int tid, int rowtile, int par,
                                            int c) {
    int tt = par + 2 * (c >> 2);
    int n0 = ((rowtile + tt) & 63) * 128;
    int kc = c & 3;
    uint32_t buf = B_base + (uint32_t)(c % 3) * B_BUF_BYTES;
#pragma unroll
    for (int i = 0; i < 8; i++) {
        int u = tid + i * 256;
        uint32_t row = (uint32_t)u >> 4, g = (uint32_t)u & 15;
        cp16(buf + row * B_PITCH_B + swz(row, g * 16),
             &g_F[(size_t)(n0 + (int)row) * NDIM + kc * 128 + (int)g * 8]);
    }
}

__global__ __launch_bounds__(256, 1) void k_infonce() {
    extern __shared__ char dyn[];
    uint32_t A_base = smem_u32(dyn);
    uint32_t B_base = A_base + A_BYTES;
    __shared__ float srow[128];

    int tid = threadIdx.x;
    int wid = tid >> 5, lane = tid & 31;
    int warpm = wid >> 1, warpn = wid & 1;  // 4 x 2
    int bid = blockIdx.x;
    int rowtile = bid >> 1, par = bid & 1;
    int m0 = rowtile * 128;
    int T = (rowtile < 32) ? 33 : 32;
    int nT = (T - par + 1) >> 1;  // tiles this CTA owns
    int C = nT * 4;               // 128-k chunks, streamed continuously

    if (tid < 128) srow[tid] = 0.f;

    // A via cp.async: 8192 16B-groups, swizzled, pitch 1024.
#pragma unroll
    for (int i = 0; i < 32; i++) {
        int u = tid + i * 256;
        uint32_t row = (uint32_t)u >> 6, g = (uint32_t)u & 63;
        cp16(A_base + row * A_PITCH_B + swz(row, g * 16),
             &g_F[(size_t)(m0 + (int)row) * NDIM + (int)g * 8]);
    }
    cp_commit();
    issue_chunk(B_base, tid, rowtile, par, 0);
    cp_commit();
    issue_chunk(B_base, tid, rowtile, par, 1);
    cp_commit();

    // ldmatrix lane addressing (swizzled).
    int rowadd = ((lane >> 3) & 1) * 8 + (lane & 7);
    int kadd = (lane >> 4) * 16;
    uint32_t xorm = ((uint32_t)lane & 7) << 4;  // rowadd&7 == lane&7

    uint32_t aRow[2];
#pragma unroll
    for (int mf = 0; mf < 2; mf++)
        aRow[mf] = A_base + (uint32_t)(warpm * 32 + mf * 16 + rowadd) * A_PITCH_B;
    uint32_t bRowRel[4];
#pragma unroll
    for (int nf = 0; nf < 4; nf++)
        bRowRel[nf] = (uint32_t)(warpn * 64 + nf * 16 + rowadd) * B_PITCH_B;

    float accRow[4] = {0.f, 0.f, 0.f, 0.f};
    int grBase = m0 + warpm * 32 + (lane >> 2);  // rows grBase + {0,8,16,24}

    float acc[2][8][4];

    for (int c = 0; c < C; ++c) {
        cp_wait<1>();     // chunk c (and A) complete; chunk c+1 may pend
        __syncthreads();  // data visible; all warps done with buf (c-3)%3
        if (c + 2 < C) issue_chunk(B_base, tid, rowtile, par, c + 2);
        cp_commit();      // exactly one group per iteration (may be empty)

        int kc = c & 3;
        int tt = par + 2 * (c >> 2);
        int n0 = ((rowtile + tt) & 63) * 128;
        if (kc == 0) {
#pragma unroll
            for (int mf = 0; mf < 2; mf++)
#pragma unroll
                for (int q = 0; q < 8; q++)
#pragma unroll
                    for (int j = 0; j < 4; j++) acc[mf][q][j] = 0.f;
        }

        uint32_t bBuf = B_base + (uint32_t)(c % 3) * B_BUF_BYTES;
#pragma unroll
        for (int ks = 0; ks < 8; ++ks) {
            uint32_t koffA = (uint32_t)(kc * 256 + ks * 32 + kadd) ^ xorm;
            uint32_t koffB = (uint32_t)(ks * 32 + kadd) ^ xorm;
            uint32_t a[2][4];
#pragma unroll
            for (int mf = 0; mf < 2; mf++)
                ldsm_x4(a[mf][0], a[mf][1], a[mf][2], a[mf][3], aRow[mf] + koffA);
#pragma unroll
            for (int nf = 0; nf < 4; nf++) {
                uint32_t b0, b1, b2, b3;
                ldsm_x4(b0, b1, b2, b3, bBuf + bRowRel[nf] + koffB);
#pragma unroll
                for (int mf = 0; mf < 2; mf++) {
                    mma16816(acc[mf][nf * 2 + 0], a[mf][0], a[mf][1], a[mf][2], a[mf][3],
                             b0, b2);
                    mma16816(acc[mf][nf * 2 + 1], a[mf][0], a[mf][1], a[mf][2], a[mf][3],
                             b1, b3);
                }
            }
        }

        if (kc != 3) continue;

        // ---------------- per-tile epilogue ----------------
        if (tt == 0) {
            // Diagonal tile: row sums only, self-similarity masked.
#pragma unroll
            for (int mf = 0; mf < 2; mf++) {
                int gr0 = grBase + mf * 16;
#pragma unroll
                for (int q = 0; q < 8; q++) {
                    int c0 = n0 + warpn * 64 + (q >> 1) * 16 + (q & 1) * 8 + 2 * (lane & 3);
#pragma unroll
                    for (int j = 0; j < 4; j++) {
                        float arg = fmaf(acc[mf][q][j], EX2_SCALE, -EX2_SCALE);
                        float e;
                        asm("ex2.approx.ftz.f32 %0, %1;" : "=f"(e) : "f"(arg));
                        int gc = c0 + (j & 1);
                        int gr = gr0 + (j >> 1) * 8;
                        if (gc != gr) accRow[mf * 2 + (j >> 1)] += e;
                    }
                }
            }
        } else {
            // Off-diagonal tile: rows (tile i) + columns (tile j).
            float colAcc[16];
#pragma unroll
            for (int x = 0; x < 16; x++) colAcc[x] = 0.f;
#pragma unroll
            for (int mf = 0; mf < 2; mf++) {
#pragma unroll
                for (int q = 0; q < 8; q++) {
#pragma unroll
                    for (int j = 0; j < 4; j++) {
                        float arg = fmaf(acc[mf][q][j], EX2_SCALE, -EX2_SCALE);
                        float e;
                        asm("ex2.approx.ftz.f32 %0, %1;" : "=f"(e) : "f"(arg));
                        accRow[mf * 2 + (j >> 1)] += e;
                        colAcc[q * 2 + (j & 1)] += e;
                    }
                }
            }
#pragma unroll
            for (int x = 0; x < 16; x++) {
                float v = colAcc[x];
                v += __shfl_xor_sync(0xFFFFFFFFu, v, 4);
                v += __shfl_xor_sync(0xFFFFFFFFu, v, 8);
                v += __shfl_xor_sync(0xFFFFFFFFu, v, 16);
                if (lane < 4) {
                    int q = x >> 1, jlo = x & 1;
                    int col = n0 + warpn * 64 + (q >> 1) * 16 + (q & 1) * 8 + 2 * lane + jlo;
                    atomicAdd(&g_rowsum[col], v);
                }
            }
        }
    }

    // Row partials: reduce into srow, then atomically to global.
    __syncthreads();
#pragma unroll
    for (int i = 0; i < 4; i++) {
        float v = accRow[i];
        v += __shfl_xor_sync(0xFFFFFFFFu, v, 1);
        v += __shfl_xor_sync(0xFFFFFFFFu, v, 2);
        if ((lane & 3) == 0)
            atomicAdd(&srow[warpm * 32 + i * 8 + (lane >> 2)], v);
    }
    __syncthreads();
    if (tid < 128)
        atomicAdd(&g_rowsum[m0 + tid], srow[tid]);
}

// ======================= kernel D: final reduction ===============
__global__ void k_finish(float* __restrict__ out) {
    int tid = threadIdx.x;  // 256, grid 32
    int r = blockIdx.x * 256 + tid;
    // LSE_r = 10 + log(sum exp(sim-10));  loss_r = LSE_r - pos-pair sim
    float acc = 10.f + __logf(g_rowsum[r]) - g_pos[r & (NB - 1)];
#pragma unroll
    for (int o = 16; o > 0; o >>= 1) acc += __shfl_xor_sync(0xFFFFFFFFu, acc, o);
    __shared__ float sred[8];
    if ((tid & 31) == 0) sred[tid >> 5] = acc;
    __syncthreads();
    if (tid == 0) {
        float s = 0.f;
#pragma unroll
        for (int i = 0; i < 8; i++) s += sred[i];
        atomicAdd(out, s * (1.f / (float)NROWS));
    }
}

// ======================= launch ==================================
extern "C" void kernel_launch(void* const* d_in, const int* in_sizes, int n_in,
                              void* d_out, int out_size) {
    const float* f1 = (const float*)d_in[0];
    const float* f2 = (const float*)d_in[1];
    float* out = (float*)d_out;

    cudaFuncSetAttribute(k_infonce, cudaFuncAttributeMaxDynamicSharedMemorySize, SMEM_DYN);

    k_zero<<<32, 256>>>(out);
    k_normalize<<<NROWS, 128>>>(f1, f2);
    k_pos<<<NB, 128>>>(f1, f2);
    k_infonce<<<128, 256, SMEM_DYN>>>();
    k_finish<<<32, 256>>>(out);
}

// round 10
// speedup vs baseline: 1.9165x; 1.0789x over previous
#include <cuda_runtime.h>
#include <cuda_bf16.h>
#include <cstdint>

// ======================= problem constants =======================
// B=4096, D=512, rows = 2B = 8192. sim = F F^T / 0.1. Fixed shift C = 10
// (cosine <= 1 exactly) removes the softmax max pass entirely.
// Symmetry: exp(sim-10) is symmetric -> each off-diagonal 128x128 tile is
// computed once and contributes to row partials (tile i) AND col partials
// (tile j). 2080 tiles total, flattened and balanced over 148 CTAs.
#define NROWS 8192
#define NDIM  512
#define NB    4096
#define EX2_SCALE 14.4269504089f
#define NTILES_TOTAL 2080
#define NCTA 148

// ======================= device scratch (no allocs allowed) =====
static __device__ __align__(16) __nv_bfloat16 g_F[NROWS * NDIM];  // 8 MB normalized bf16
static __device__ float g_pos[NB];        // exact fp32 pos-pair sim/T
static __device__ float g_rowsum[NROWS];  // sum_c!=r exp(sim-10), atomically accumulated

// ======================= PTX helpers (non-'a' features only) =====
__device__ __forceinline__ uint32_t smem_u32(const void* p) {
    uint32_t a;
    asm("{ .reg .u64 t; cvta.to.shared.u64 t, %1; cvt.u32.u64 %0, t; }" : "=r"(a) : "l"(p));
    return a;
}
__device__ __forceinline__ void cp16(uint32_t saddr, const void* g) {
    asm volatile("cp.async.cg.shared.global [%0], [%1], 16;" :: "r"(saddr), "l"(g));
}
__device__ __forceinline__ void cp_commit() { asm volatile("cp.async.commit_group;" ::: "memory"); }
template <int N>
__device__ __forceinline__ void cp_wait() { asm volatile("cp.async.wait_group %0;" :: "n"(N) : "memory"); }

__device__ __forceinline__ void ldsm_x4(uint32_t& r0, uint32_t& r1, uint32_t& r2, uint32_t& r3,
                                        uint32_t addr) {
    asm volatile("ldmatrix.sync.aligned.m8n8.x4.shared.b16 {%0,%1,%2,%3}, [%4];"
                 : "=r"(r0), "=r"(r1), "=r"(r2), "=r"(r3)
                 : "r"(addr));
}
__device__ __forceinline__ void mma16816(float* d, uint32_t a0, uint32_t a1, uint32_t a2,
                                         uint32_t a3, uint32_t b0, uint32_t b1) {
    asm volatile(
        "mma.sync.aligned.m16n8k16.row.col.f32.bf16.bf16.f32 "
        "{%0,%1,%2,%3}, {%4,%5,%6,%7}, {%8,%9}, {%0,%1,%2,%3};"
        : "+f"(d[0]), "+f"(d[1]), "+f"(d[2]), "+f"(d[3])
        : "r"(a0), "r"(a1), "r"(a2), "r"(a3), "r"(b0), "r"(b1));
}

// Global symmetric-tile list: rowtiles i<32 own t=0..32 (33 tiles, incl.
// the wrap pair {i,i+32} at t=32), i>=32 own t=0..31.
__device__ __forceinline__ void decode_tile(int idx, int& i, int& t) {
    if (idx < 1056) { i = idx / 33; t = idx - 33 * i; }
    else { int r = idx - 1056; i = 32 + (r >> 5); t = r & 31; }
}

// ======================= kernel A: normalize -> bf16 (+zero) =====
__global__ void k_normalize(const float* __restrict__ f1, const float* __restrict__ f2,
                            float* __restrict__ out) {
    int row = blockIdx.x;  // 0..8191
    int tid = threadIdx.x;  // 128
    if (tid == 0) g_rowsum[row] = 0.f;    // fold k_zero in here
    if (row == 0 && tid == 1) out[0] = 0.f;
    const float* src = (row < NB) ? (f1 + (size_t)row * NDIM)
                                  : (f2 + (size_t)(row - NB) * NDIM);
    float v[4];
    float ss = 0.f;
#pragma unroll
    for (int i = 0; i < 4; i++) {
        v[i] = src[tid + i * 128];
        ss += v[i] * v[i];
    }
#pragma unroll
    for (int o = 16; o > 0; o >>= 1) ss += __shfl_xor_sync(0xFFFFFFFFu, ss, o);
    __shared__ float sred[4];
    if ((tid & 31) == 0) sred[tid >> 5] = ss;
    __syncthreads();
    float tot = sred[0] + sred[1] + sred[2] + sred[3];
    float scale = 1.f / fmaxf(sqrtf(tot), 1e-12f);
#pragma unroll
    for (int i = 0; i < 4; i++)
        g_F[(size_t)row * NDIM + tid + i * 128] = __float2bfloat16(v[i] * scale);
}

// ======================= kernel B: exact positive-pair sims ======
__global__ void k_pos(const float* __restrict__ f1, const float* __restrict__ f2) {
    int i = blockIdx.x;  // 0..4095
    int tid = threadIdx.x;  // 128
    const float* a = f1 + (size_t)i * NDIM;
    const float* b = f2 + (size_t)i * NDIM;
    float s11 = 0.f, s22 = 0.f, s12 = 0.f;
#pragma unroll
    for (int c = tid; c < NDIM; c += 128) {
        float x = a[c], y = b[c];
        s11 += x * x; s22 += y * y; s12 += x * y;
    }
#pragma unroll
    for (int o = 16; o > 0; o >>= 1) {
        s11 += __shfl_xor_sync(0xFFFFFFFFu, s11, o);
        s22 += __shfl_xor_sync(0xFFFFFFFFu, s22, o);
        s12 += __shfl_xor_sync(0xFFFFFFFFu, s12, o);
    }
    __shared__ float r11[4], r22[4], r12[4];
    if ((tid & 31) == 0) { r11[tid >> 5] = s11; r22[tid >> 5] = s22; r12[tid >> 5] = s12; }
    __syncthreads();
    if (tid == 0) {
        float t11 = r11[0] + r11[1] + r11[2] + r11[3];
        float t22 = r22[0] + r22[1] + r22[2] + r22[3];
        float t12 = r12[0] + r12[1] + r12[2] + r12[3];
        float inv1 = 1.f / fmaxf(sqrtf(t11), 1e-12f);
        float inv2 = 1.f / fmaxf(sqrtf(t22), 1e-12f);
        g_pos[i] = t12 * inv1 * inv2 * 10.f;  // sim/T
    }
}

// ======================= kernel C: symmetric fused GEMM + exp-sum
// 148 CTAs; CTA g owns global tiles [g*2080/148, (g+1)*2080/148) -> 14-15
// tiles, spanning <=2 rowtiles (<=1 A reload at a drained boundary).
// SMEM: A 128x512 bf16 pitch 1024B XOR-swizzled (128 KB); B 3-deep ring of
// 128x128 chunks pitch 256B (96 KB). Continuous chunk stream per segment:
// 1 cp_wait + 1 syncthreads per chunk, prefetch distance 2, and explicit
// fragment double-buffering in the ks loop (16 MMAs cover ldsm latency).
static constexpr int A_PITCH_B = 1024;
static constexpr int B_PITCH_B = 256;
static constexpr int A_BYTES = 128 * A_PITCH_B;             // 131072
static constexpr int B_BUF_BYTES = 128 * B_PITCH_B;         // 32768
static constexpr int SMEM_DYN = A_BYTES + 3 * B_BUF_BYTES;  // 229376

// swizzle: XOR 16B-group index with (row & 7)
__device__ __forceinline__ uint32_t swz(uint32_t row, uint32_t byteoff) {
    return byteoff ^ ((row & 7) << 4);
}

__device__ __forceinline__ void issue_chunk(uint32_t B_base, int tid, int i, int t0, int c) {
    int t = t0 + (c >> 2);
    int n0 = ((i + t) & 63) * 128;
    int kc = c & 3;
    uint32_t buf = B_base + (uint32_t)(c % 3) * B_BUF_BYTES;
#pragma unroll
    for (int u = 0; u < 8; u++) {
        int x = tid + u * 256;
        uint32_t row = (uint32_t)x >> 4, g = (uint32_t)x & 15;
        cp16(buf + row * B_PITCH_B + swz(row, g * 16),
             &g_F[(size_t)(n0 + (int)row) * NDIM + kc * 128 + (int)g * 8]);
    }
}

__global__ __launch_bounds__(256, 1) void k_infonce() {
    extern __shared__ char dyn[];
    uint32_t A_base = smem_u32(dyn);
    uint32_t B_base = A_base + A_BYTES;
    __shared__ float srow[128];

    int tid = threadIdx.x;
    int wid = tid >> 5, lane = tid & 31;
    int warpm = wid >> 1, warpn = wid & 1;  // 4 x 2
    int g = blockIdx.x;
    int s = (g * NTILES_TOTAL) / NCTA;
    int e = ((g + 1) * NTILES_TOTAL) / NCTA;

    // ldmatrix lane addressing (swizzled).
    int rowadd = ((lane >> 3) & 1) * 8 + (lane & 7);
    int kadd = (lane >> 4) * 16;
    uint32_t xorm = ((uint32_t)lane & 7) << 4;  // rowadd&7 == lane&7

    uint32_t aRow[2];
#pragma unroll
    for (int mf = 0; mf < 2; mf++)
        aRow[mf] = A_base + (uint32_t)(warpm * 32 + mf * 16 + rowadd) * A_PITCH_B;
    uint32_t bRowRel[4];
#pragma unroll
    for (int nf = 0; nf < 4; nf++)
        bRowRel[nf] = (uint32_t)(warpn * 64 + nf * 16 + rowadd) * B_PITCH_B;

    float acc[2][8][4];
    uint32_t af[2][2][4], bf[2][4][4];

    while (s < e) {
        int rowtile, t0;
        decode_tile(s, rowtile, t0);
        int Trow = (rowtile < 32) ? 33 : 32;
        int ntiles = min(e - s, Trow - t0);
        s += ntiles;
        int C = ntiles * 4;
        int m0 = rowtile * 128;
        int grBase = m0 + warpm * 32 + (lane >> 2);
        float accRow[4] = {0.f, 0.f, 0.f, 0.f};

        if (tid < 128) srow[tid] = 0.f;

        // A via cp.async: 8192 16B-groups, swizzled, pitch 1024. Safe: all
        // warps are past the previous segment's MMAs (row-flush barrier).
#pragma unroll
        for (int u = 0; u < 32; u++) {
            int x = tid + u * 256;
            uint32_t row = (uint32_t)x >> 6, gg = (uint32_t)x & 63;
            cp16(A_base + row * A_PITCH_B + swz(row, gg * 16),
                 &g_F[(size_t)(m0 + (int)row) * NDIM + (int)gg * 8]);
        }
        cp_commit();
        issue_chunk(B_base, tid, rowtile, t0, 0);
        cp_commit();
        issue_chunk(B_base, tid, rowtile, t0, 1);
        cp_commit();

        for (int c = 0; c < C; ++c) {
            cp_wait<1>();     // chunk c (and A) complete; chunk c+1 may pend
            __syncthreads();  // visible to all; buf (c-1)%3 free for c+2
            if (c + 2 < C) issue_chunk(B_base, tid, rowtile, t0, c + 2);
            cp_commit();      // one group per iteration (possibly empty)

            int kc = c & 3;
            int t = t0 + (c >> 2);
            int n0 = ((rowtile + t) & 63) * 128;
            if (kc == 0) {
#pragma unroll
                for (int mf = 0; mf < 2; mf++)
#pragma unroll
                    for (int q = 0; q < 8; q++)
#pragma unroll
                        for (int j = 0; j < 4; j++) acc[mf][q][j] = 0.f;
            }

            uint32_t bBuf = B_base + (uint32_t)(c % 3) * B_BUF_BYTES;

            // Fragment double-buffered ks loop: ldsm for ks+1 issued before
            // the 16 MMAs of ks (MMA issue covers ldsm latency).
            {
                uint32_t koffA = (uint32_t)(kc * 256 + kadd) ^ xorm;
                uint32_t koffB = (uint32_t)kadd ^ xorm;
#pragma unroll
                for (int mf = 0; mf < 2; mf++)
                    ldsm_x4(af[0][mf][0], af[0][mf][1], af[0][mf][2], af[0][mf][3],
                            aRow[mf] + koffA);
#pragma unroll
                for (int nf = 0; nf < 4; nf++)
                    ldsm_x4(bf[0][nf][0], bf[0][nf][1], bf[0][nf][2], bf[0][nf][3],
                            bBuf + bRowRel[nf] + koffB);
            }
#pragma unroll
            for (int ks = 0; ks < 8; ++ks) {
                int cur = ks & 1, nxt = cur ^ 1;
                if (ks < 7) {
                    uint32_t koffA = (uint32_t)(kc * 256 + (ks + 1) * 32 + kadd) ^ xorm;
                    uint32_t koffB = (uint32_t)((ks + 1) * 32 + kadd) ^ xorm;
#pragma unroll
                    for (int mf = 0; mf < 2; mf++)
                        ldsm_x4(af[nxt][mf][0], af[nxt][mf][1], af[nxt][mf][2], af[nxt][mf][3],
                                aRow[mf] + koffA);
#pragma unroll
                    for (int nf = 0; nf < 4; nf++)
                        ldsm_x4(bf[nxt][nf][0], bf[nxt][nf][1], bf[nxt][nf][2], bf[nxt][nf][3],
                                bBuf + bRowRel[nf] + koffB);
                }
#pragma unroll
                for (int nf = 0; nf < 4; nf++) {
#pragma unroll
                    for (int mf = 0; mf < 2; mf++) {
                        mma16816(acc[mf][nf * 2 + 0], af[cur][mf][0], af[cur][mf][1],
                                 af[cur][mf][2], af[cur][mf][3], bf[cur][nf][0], bf[cur][nf][2]);
                        mma16816(acc[mf][nf * 2 + 1], af[cur][mf][0], af[cur][mf][1],
                                 af[cur][mf][2], af[cur][mf][3], bf[cur][nf][1], bf[cur][nf][3]);
                    }
                }
            }

            if (kc != 3) continue;

            // ---------------- per-tile epilogue ----------------
            if (t == 0) {
                // Diagonal tile: row sums only, self-similarity masked.
#pragma unroll
                for (int mf = 0; mf < 2; mf++) {
                    int gr0 = grBase + mf * 16;
#pragma unroll
                    for (int q = 0; q < 8; q++) {
                        int c0 = n0 + warpn * 64 + (q >> 1) * 16 + (q & 1) * 8 + 2 * (lane & 3);
#pragma unroll
                        for (int j = 0; j < 4; j++) {
                            float arg = fmaf(acc[mf][q][j], EX2_SCALE, -EX2_SCALE);
                            float ev;
                            asm("ex2.approx.ftz.f32 %0, %1;" : "=f"(ev) : "f"(arg));
                            int gc = c0 + (j & 1);
                            int gr = gr0 + (j >> 1) * 8;
                            if (gc != gr) accRow[mf * 2 + (j >> 1)] += ev;
                        }
                    }
                }
            } else {
                // Off-diagonal tile: rows (tile i) + columns (tile j).
                float colAcc[16];
#pragma unroll
                for (int x = 0; x < 16; x++) colAcc[x] = 0.f;
#pragma unroll
                for (int mf = 0; mf < 2; mf++) {
#pragma unroll
                    for (int q = 0; q < 8; q++) {
#pragma unroll
                        for (int j = 0; j < 4; j++) {
                            float arg = fmaf(acc[mf][q][j], EX2_SCALE, -EX2_SCALE);
                            float ev;
                            asm("ex2.approx.ftz.f32 %0, %1;" : "=f"(ev) : "f"(arg));
                            accRow[mf * 2 + (j >> 1)] += ev;
                            colAcc[q * 2 + (j & 1)] += ev;
                        }
                    }
                }
#pragma unroll
                for (int x = 0; x < 16; x++) {
                    float v = colAcc[x];
                    v += __shfl_xor_sync(0xFFFFFFFFu, v, 4);
                    v += __shfl_xor_sync(0xFFFFFFFFu, v, 8);
                    v += __shfl_xor_sync(0xFFFFFFFFu, v, 16);
                    if (lane < 4) {
                        int q = x >> 1, jlo = x & 1;
                        int col = n0 + warpn * 64 + (q >> 1) * 16 + (q & 1) * 8 + 2 * lane + jlo;
                        atomicAdd(&g_rowsum[col], v);
                    }
                }
            }
        }

        // Segment row flush (also the drain barrier before next A reload).
        __syncthreads();
#pragma unroll
        for (int x = 0; x < 4; x++) {
            float v = accRow[x];
            v += __shfl_xor_sync(0xFFFFFFFFu, v, 1);
            v += __shfl_xor_sync(0xFFFFFFFFu, v, 2);
            if ((lane & 3) == 0)
                atomicAdd(&srow[warpm * 32 + x * 8 + (lane >> 2)], v);
        }
        __syncthreads();
        if (tid < 128)
            atomicAdd(&g_rowsum[m0 + tid], srow[tid]);
    }
}

// ======================= kernel D: final reduction ===============
__global__ void k_finish(float* __restrict__ out) {
    int tid = threadIdx.x;  // 256, grid 32
    int r = blockIdx.x * 256 + tid;
    // LSE_r = 10 + log(sum exp(sim-10));  loss_r = LSE_r - pos-pair sim
    float acc = 10.f + __logf(g_rowsum[r]) - g_pos[r & (NB - 1)];
#pragma unroll
    for (int o = 16; o > 0; o >>= 1) acc += __shfl_xor_sync(0xFFFFFFFFu, acc, o);
    __shared__ float sred[8];
    if ((tid & 31) == 0) sred[tid >> 5] = acc;
    __syncthreads();
    if (tid == 0) {
        float s = 0.f;
#pragma unroll
        for (int i = 0; i < 8; i++) s += sred[i];
        atomicAdd(out, s * (1.f / (float)NROWS));
    }
}

// ======================= launch ==================================
extern "C" void kernel_launch(void* const* d_in, const int* in_sizes, int n_in,
                              void* d_out, int out_size) {
    const float* f1 = (const float*)d_in[0];
    const float* f2 = (const float*)d_in[1];
    float* out = (float*)d_out;

    cudaFuncSetAttribute(k_infonce, cudaFuncAttributeMaxDynamicSharedMemorySize, SMEM_DYN);

    k_normalize<<<NROWS, 128>>>(f1, f2, out);
    k_pos<<<NB, 128>>>(f1, f2);
    k_infonce<<<NCTA, 256, SMEM_DYN>>>();
    k_finish<<<32, 256>>>(out);
}

// round 11
// speedup vs baseline: 1.9845x; 1.0355x over previous
#include <cuda_runtime.h>
#include <cuda_bf16.h>
#include <cstdint>

// ======================= problem constants =======================
// B=4096, D=512, rows = 2B = 8192. sim = F F^T / 0.1. Fixed shift C = 10
// (cosine <= 1 exactly) removes the softmax max pass entirely.
// Symmetry: 2080 128x128 tiles (each unordered pair once), balanced over
// 148 CTAs. FP8 path: features scaled x16, quantized e4m3; sim = D/256.
#define NROWS 8192
#define NDIM  512
#define NB    4096
// arg = D * (10/256)*log2(e) - 10*log2(e)
#define EX2_A 0.05635527503f
#define EX2_B -14.4269504089f
#define NTILES_TOTAL 2080
#define NCTA 148

// ======================= device scratch (no allocs allowed) =====
static __device__ __align__(16) uint8_t g_F8[NROWS * NDIM];  // 4 MB e4m3 (x16 scale)
static __device__ float g_pos[NB];        // exact fp32 pos-pair sim/T
static __device__ float g_rowsum[NROWS];  // sum_c!=r exp(sim-10), atomic

// ======================= PTX helpers (non-'a' features only) =====
__device__ __forceinline__ uint32_t smem_u32(const void* p) {
    uint32_t a;
    asm("{ .reg .u64 t; cvta.to.shared.u64 t, %1; cvt.u32.u64 %0, t; }" : "=r"(a) : "l"(p));
    return a;
}
__device__ __forceinline__ void cp16(uint32_t saddr, const void* g) {
    asm volatile("cp.async.cg.shared.global [%0], [%1], 16;" :: "r"(saddr), "l"(g));
}
__device__ __forceinline__ void cp_commit() { asm volatile("cp.async.commit_group;" ::: "memory"); }
template <int N>
__device__ __forceinline__ void cp_wait() { asm volatile("cp.async.wait_group %0;" :: "n"(N) : "memory"); }

__device__ __forceinline__ void ldsm_x4(uint32_t& r0, uint32_t& r1, uint32_t& r2, uint32_t& r3,
                                        uint32_t addr) {
    asm volatile("ldmatrix.sync.aligned.m8n8.x4.shared.b16 {%0,%1,%2,%3}, [%4];"
                 : "=r"(r0), "=r"(r1), "=r"(r2), "=r"(r3)
                 : "r"(addr));
}
// fp8 e4m3 MMA, k=32. Fragment layout identical to bf16 m16n8k16 pattern
// with 2 fp8 packed per b16 lane element (so the same ldmatrix.b16 works).
__device__ __forceinline__ void mma16832(float* d, uint32_t a0, uint32_t a1, uint32_t a2,
                                         uint32_t a3, uint32_t b0, uint32_t b1) {
    asm volatile(
        "mma.sync.aligned.m16n8k32.row.col.f32.e4m3.e4m3.f32 "
        "{%0,%1,%2,%3}, {%4,%5,%6,%7}, {%8,%9}, {%0,%1,%2,%3};"
        : "+f"(d[0]), "+f"(d[1]), "+f"(d[2]), "+f"(d[3])
        : "r"(a0), "r"(a1), "r"(a2), "r"(a3), "r"(b0), "r"(b1));
}
// pack two f32 -> e4m3x2 (first PTX source -> high byte)
__device__ __forceinline__ uint32_t pack_e4m3x4(float x0, float x1, float x2, float x3) {
    uint16_t lo, hi;
    asm("cvt.rn.satfinite.e4m3x2.f32 %0, %1, %2;" : "=h"(lo) : "f"(x1), "f"(x0));
    asm("cvt.rn.satfinite.e4m3x2.f32 %0, %1, %2;" : "=h"(hi) : "f"(x3), "f"(x2));
    return (uint32_t)lo | ((uint32_t)hi << 16);
}

// Global symmetric-tile list: rowtiles i<32 own t=0..32 (33 tiles, incl.
// the wrap pair {i,i+32} at t=32), i>=32 own t=0..31.
__device__ __forceinline__ void decode_tile(int idx, int& i, int& t) {
    if (idx < 1056) { i = idx / 33; t = idx - 33 * i; }
    else { int r = idx - 1056; i = 32 + (r >> 5); t = r & 31; }
}

// ======================= kernel A: normalize -> e4m3 (+zero) =====
__global__ void k_normalize(const float* __restrict__ f1, const float* __restrict__ f2,
                            float* __restrict__ out) {
    int row = blockIdx.x;  // 0..8191
    int tid = threadIdx.x;  // 128
    if (tid == 0) g_rowsum[row] = 0.f;  // fold k_zero in here
    if (row == 0 && tid == 1) out[0] = 0.f;
    const float* src = (row < NB) ? (f1 + (size_t)row * NDIM)
                                  : (f2 + (size_t)(row - NB) * NDIM);
    // Each thread owns 4 CONTIGUOUS cols (4t..4t+3) for fp8 byte packing.
    float4 v = *reinterpret_cast<const float4*>(src + tid * 4);
    float ss = v.x * v.x + v.y * v.y + v.z * v.z + v.w * v.w;
#pragma unroll
    for (int o = 16; o > 0; o >>= 1) ss += __shfl_xor_sync(0xFFFFFFFFu, ss, o);
    __shared__ float sred[4];
    if ((tid & 31) == 0) sred[tid >> 5] = ss;
    __syncthreads();
    float tot = sred[0] + sred[1] + sred[2] + sred[3];
    // x16 scale into e4m3 sweet spot (elements ~0.7, max ~3; range 448).
    float scale = 16.f / fmaxf(sqrtf(tot), 1e-12f);
    uint32_t p = pack_e4m3x4(v.x * scale, v.y * scale, v.z * scale, v.w * scale);
    reinterpret_cast<uint32_t*>(g_F8)[(size_t)row * (NDIM / 4) + tid] = p;
}

// ======================= kernel B: exact positive-pair sims ======
__global__ void k_pos(const float* __restrict__ f1, const float* __restrict__ f2) {
    int i = blockIdx.x;  // 0..4095
    int tid = threadIdx.x;  // 128
    const float* a = f1 + (size_t)i * NDIM;
    const float* b = f2 + (size_t)i * NDIM;
    float s11 = 0.f, s22 = 0.f, s12 = 0.f;
#pragma unroll
    for (int c = tid; c < NDIM; c += 128) {
        float x = a[c], y = b[c];
        s11 += x * x; s22 += y * y; s12 += x * y;
    }
#pragma unroll
    for (int o = 16; o > 0; o >>= 1) {
        s11 += __shfl_xor_sync(0xFFFFFFFFu, s11, o);
        s22 += __shfl_xor_sync(0xFFFFFFFFu, s22, o);
        s12 += __shfl_xor_sync(0xFFFFFFFFu, s12, o);
    }
    __shared__ float r11[4], r22[4], r12[4];
    if ((tid & 31) == 0) { r11[tid >> 5] = s11; r22[tid >> 5] = s22; r12[tid >> 5] = s12; }
    __syncthreads();
    if (tid == 0) {
        float t11 = r11[0] + r11[1] + r11[2] + r11[3];
        float t22 = r22[0] + r22[1] + r22[2] + r22[3];
        float t12 = r12[0] + r12[1] + r12[2] + r12[3];
        float inv1 = 1.f / fmaxf(sqrtf(t11), 1e-12f);
        float inv2 = 1.f / fmaxf(sqrtf(t22), 1e-12f);
        g_pos[i] = t12 * inv1 * inv2 * 10.f;  // sim/T
    }
}

// ======================= kernel C: symmetric fused GEMM + exp-sum
// FP8 path. 148 CTAs; CTA g owns tiles [g*2080/148,(g+1)*2080/148).
// SMEM: A 128x512 e4m3 pitch 512B swizzled (64 KB); B 3-ring of 128x256
// fp8-k chunks pitch 256B (96 KB). 2 chunks per tile; per chunk: 8 ks
// steps of k=32 (32-byte stride), 16 MMAs per ks, fragments double-
// buffered so 16 MMAs cover the 6 ldsm of the next step.
static constexpr int A_PITCH_B = 512;
static constexpr int B_PITCH_B = 256;
static constexpr int A_BYTES = 128 * A_PITCH_B;             // 65536
static constexpr int B_BUF_BYTES = 128 * B_PITCH_B;         // 32768
static constexpr int SMEM_DYN = A_BYTES + 3 * B_BUF_BYTES;  // 163840

// swizzle: XOR 16B-group index with (row & 7)
__device__ __forceinline__ uint32_t swz(uint32_t row, uint32_t byteoff) {
    return byteoff ^ ((row & 7) << 4);
}

__device__ __forceinline__ void issue_chunk(uint32_t B_base, int tid, int i, int t0, int c) {
    int t = t0 + (c >> 1);
    int n0 = ((i + t) & 63) * 128;
    int kc = c & 1;  // 256 fp8-k per chunk
    uint32_t buf = B_base + (uint32_t)(c % 3) * B_BUF_BYTES;
#pragma unroll
    for (int u = 0; u < 8; u++) {
        int x = tid + u * 256;
        uint32_t row = (uint32_t)x >> 4, g = (uint32_t)x & 15;
        cp16(buf + row * B_PITCH_B + swz(row, g * 16),
             &g_F8[(size_t)(n0 + (int)row) * NDIM + kc * 256 + (int)g * 16]);
    }
}

__global__ __launch_bounds__(256, 1) void k_infonce() {
    extern __shared__ char dyn[];
    uint32_t A_base = smem_u32(dyn);
    uint32_t B_base = A_base + A_BYTES;
    __shared__ float srow[128];

    int tid = threadIdx.x;
    int wid = tid >> 5, lane = tid & 31;
    int warpm = wid >> 1, warpn = wid & 1;  // 4 x 2
    int g = blockIdx.x;
    int s = (g * NTILES_TOTAL) / NCTA;
    int e = ((g + 1) * NTILES_TOTAL) / NCTA;

    // ldmatrix lane addressing (b16 elements = fp8 pairs; swizzled).
    int rowadd = ((lane >> 3) & 1) * 8 + (lane & 7);
    int kadd = (lane >> 4) * 16;
    uint32_t xorm = ((uint32_t)lane & 7) << 4;  // rowadd&7 == lane&7

    uint32_t aRow[2];
#pragma unroll
    for (int mf = 0; mf < 2; mf++)
        aRow[mf] = A_base + (uint32_t)(warpm * 32 + mf * 16 + rowadd) * A_PITCH_B;
    uint32_t bRowRel[4];
#pragma unroll
    for (int nf = 0; nf < 4; nf++)
        bRowRel[nf] = (uint32_t)(warpn * 64 + nf * 16 + rowadd) * B_PITCH_B;

    float acc[2][8][4];
    uint32_t af[2][2][4], bf[2][4][4];

    while (s < e) {
        int rowtile, t0;
        decode_tile(s, rowtile, t0);
        int Trow = (rowtile < 32) ? 33 : 32;
        int ntiles = min(e - s, Trow - t0);
        s += ntiles;
        int C = ntiles * 2;  // 256-k chunks
        int m0 = rowtile * 128;
        int grBase = m0 + warpm * 32 + (lane >> 2);
        float accRow[4] = {0.f, 0.f, 0.f, 0.f};

        if (tid < 128) srow[tid] = 0.f;

        // A via cp.async: 64 KB, 4096 16B-groups, swizzled, pitch 512.
#pragma unroll
        for (int u = 0; u < 16; u++) {
            int x = tid + u * 256;
            uint32_t row = (uint32_t)x >> 5, gg = (uint32_t)x & 31;
            cp16(A_base + row * A_PITCH_B + swz(row, gg * 16),
                 &g_F8[(size_t)(m0 + (int)row) * NDIM + (int)gg * 16]);
        }
        cp_commit();
        issue_chunk(B_base, tid, rowtile, t0, 0);
        cp_commit();
        issue_chunk(B_base, tid, rowtile, t0, 1);
        cp_commit();

        for (int c = 0; c < C; ++c) {
            cp_wait<1>();     // chunk c (and A) complete; chunk c+1 may pend
            __syncthreads();  // visible to all; buf (c-1)%3 free for c+2
            if (c + 2 < C) issue_chunk(B_base, tid, rowtile, t0, c + 2);
            cp_commit();      // one group per iteration (possibly empty)

            int kc = c & 1;
            int t = t0 + (c >> 1);
            int n0 = ((rowtile + t) & 63) * 128;
            if (kc == 0) {
#pragma unroll
                for (int mf = 0; mf < 2; mf++)
#pragma unroll
                    for (int q = 0; q < 8; q++)
#pragma unroll
                        for (int j = 0; j < 4; j++) acc[mf][q][j] = 0.f;
            }

            uint32_t bBuf = B_base + (uint32_t)(c % 3) * B_BUF_BYTES;

            // Fragment double-buffered ks loop (k=32 fp8 = 32B per step).
            {
                uint32_t koffA = (uint32_t)(kc * 256 + kadd) ^ xorm;
                uint32_t koffB = (uint32_t)kadd ^ xorm;
#pragma unroll
                for (int mf = 0; mf < 2; mf++)
                    ldsm_x4(af[0][mf][0], af[0][mf][1], af[0][mf][2], af[0][mf][3],
                            aRow[mf] + koffA);
#pragma unroll
                for (int nf = 0; nf < 4; nf++)
                    ldsm_x4(bf[0][nf][0], bf[0][nf][1], bf[0][nf][2], bf[0][nf][3],
                            bBuf + bRowRel[nf] + koffB);
            }
#pragma unroll
            for (int ks = 0; ks < 8; ++ks) {
                int cur = ks & 1, nxt = cur ^ 1;
                if (ks < 7) {
                    uint32_t koffA = (uint32_t)(kc * 256 + (ks + 1) * 32 + kadd) ^ xorm;
                    uint32_t koffB = (uint32_t)((ks + 1) * 32 + kadd) ^ xorm;
#pragma unroll
                    for (int mf = 0; mf < 2; mf++)
                        ldsm_x4(af[nxt][mf][0], af[nxt][mf][1], af[nxt][mf][2], af[nxt][mf][3],
                                aRow[mf] + koffA);
#pragma unroll
                    for (int nf = 0; nf < 4; nf++)
                        ldsm_x4(bf[nxt][nf][0], bf[nxt][nf][1], bf[nxt][nf][2], bf[nxt][nf][3],
                                bBuf + bRowRel[nf] + koffB);
                }
#pragma unroll
                for (int nf = 0; nf < 4; nf++) {
#pragma unroll
                    for (int mf = 0; mf < 2; mf++) {
                        mma16832(acc[mf][nf * 2 + 0], af[cur][mf][0], af[cur][mf][1],
                                 af[cur][mf][2], af[cur][mf][3], bf[cur][nf][0], bf[cur][nf][2]);
                        mma16832(acc[mf][nf * 2 + 1], af[cur][mf][0], af[cur][mf][1],
                                 af[cur][mf][2], af[cur][mf][3], bf[cur][nf][1], bf[cur][nf][3]);
                    }
                }
            }

            if (kc != 1) continue;

            // ---------------- per-tile epilogue ----------------
            if (t == 0) {
                // Diagonal tile: row sums only, self-similarity masked.
#pragma unroll
                for (int mf = 0; mf < 2; mf++) {
                    int gr0 = grBase + mf * 16;
#pragma unroll
                    for (int q = 0; q < 8; q++) {
                        int c0 = n0 + warpn * 64 + (q >> 1) * 16 + (q & 1) * 8 + 2 * (lane & 3);
#pragma unroll
                        for (int j = 0; j < 4; j++) {
                            float arg = fmaf(acc[mf][q][j], EX2_A, EX2_B);
                            float ev;
                            asm("ex2.approx.ftz.f32 %0, %1;" : "=f"(ev) : "f"(arg));
                            int gc = c0 + (j & 1);
                            int gr = gr0 + (j >> 1) * 8;
                            if (gc != gr) accRow[mf * 2 + (j >> 1)] += ev;
                        }
                    }
                }
            } else {
                // Off-diagonal tile: rows (tile i) + columns (tile j).
                float colAcc[16];
#pragma unroll
                for (int x = 0; x < 16; x++) colAcc[x] = 0.f;
#pragma unroll
                for (int mf = 0; mf < 2; mf++) {
#pragma unroll
                    for (int q = 0; q < 8; q++) {
#pragma unroll
                        for (int j = 0; j < 4; j++) {
                            float arg = fmaf(acc[mf][q][j], EX2_A, EX2_B);
                            float ev;
                            asm("ex2.approx.ftz.f32 %0, %1;" : "=f"(ev) : "f"(arg));
                            accRow[mf * 2 + (j >> 1)] += ev;
                            colAcc[q * 2 + (j & 1)] += ev;
                        }
                    }
                }
#pragma unroll
                for (int x = 0; x < 16; x++) {
                    float v = colAcc[x];
                    v += __shfl_xor_sync(0xFFFFFFFFu, v, 4);
                    v += __shfl_xor_sync(0xFFFFFFFFu, v, 8);
                    v += __shfl_xor_sync(0xFFFFFFFFu, v, 16);
                    if (lane < 4) {
                        int q = x >> 1, jlo = x & 1;
                        int col = n0 + warpn * 64 + (q >> 1) * 16 + (q & 1) * 8 + 2 * lane + jlo;
                        atomicAdd(&g_rowsum[col], v);
                    }
                }
            }
        }

        // Segment row flush (also the drain barrier before next A reload).
        __syncthreads();
#pragma unroll
        for (int x = 0; x < 4; x++) {
            float v = accRow[x];
            v += __shfl_xor_sync(0xFFFFFFFFu, v, 1);
            v += __shfl_xor_sync(0xFFFFFFFFu, v, 2);
            if ((lane & 3) == 0)
                atomicAdd(&srow[warpm * 32 + x * 8 + (lane >> 2)], v);
        }
        __syncthreads();
        if (tid < 128)
            atomicAdd(&g_rowsum[m0 + tid], srow[tid]);
    }
}

// ======================= kernel D: final reduction ===============
__global__ void k_finish(float* __restrict__ out) {
    int tid = threadIdx.x;  // 256, grid 32
    int r = blockIdx.x * 256 + tid;
    // LSE_r = 10 + log(sum exp(sim-10));  loss_r = LSE_r - pos-pair sim
    float acc = 10.f + __logf(g_rowsum[r]) - g_pos[r & (NB - 1)];
#pragma unroll
    for (int o = 16; o > 0; o >>= 1) acc += __shfl_xor_sync(0xFFFFFFFFu, acc, o);
    __shared__ float sred[8];
    if ((tid & 31) == 0) sred[tid >> 5] = acc;
    __syncthreads();
    if (tid == 0) {
        float s = 0.f;
#pragma unroll
        for (int i = 0; i < 8; i++) s += sred[i];
        atomicAdd(out, s * (1.f / (float)NROWS));
    }
}

// ======================= launch ==================================
extern "C" void kernel_launch(void* const* d_in, const int* in_sizes, int n_in,
                              void* d_out, int out_size) {
    const float* f1 = (const float*)d_in[0];
    const float* f2 = (const float*)d_in[1];
    float* out = (float*)d_out;

    cudaFuncSetAttribute(k_infonce, cudaFuncAttributeMaxDynamicSharedMemorySize, SMEM_DYN);

    k_normalize<<<NROWS, 128>>>(f1, f2, out);
    k_pos<<<NB, 128>>>(f1, f2);
    k_infonce<<<NCTA, 256, SMEM_DYN>>>();
    k_finish<<<32, 256>>>(out);
}

// round 13
// speedup vs baseline: 2.0636x; 1.0398x over previous
#include <cuda_runtime.h>
#include <cuda_bf16.h>
#include <cstdint>

// ======================= problem constants =======================
// B=4096, D=512, rows = 2B = 8192. sim = F F^T / 0.1. Fixed shift C = 10
// (cosine <= 1 exactly) removes the softmax max pass entirely.
// Symmetry: 2080 128x128 tiles (each unordered pair once), balanced over
// 148 CTAs. FP8 path: features scaled x16, quantized e4m3; sim = D/256.
#define NROWS 8192
#define NDIM  512
#define NB    4096
// arg = D * (10/256)*log2(e) - 10*log2(e)
#define EX2_A 0.05635527503f
#define EX2_B -14.4269504089f
#define NTILES_TOTAL 2080
#define NCTA 148
#define NTHREADS 512

// ======================= device scratch (no allocs allowed) =====
static __device__ __align__(16) uint8_t g_F8[NROWS * NDIM];  // 4 MB e4m3 (x16 scale)
static __device__ float g_pos[NB];        // exact fp32 pos-pair sim/T
static __device__ float g_rowsum[NROWS];  // sum_c!=r exp(sim-10), atomic

// ======================= PTX helpers (non-'a' features only) =====
__device__ __forceinline__ uint32_t smem_u32(const void* p) {
    uint32_t a;
    asm("{ .reg .u64 t; cvta.to.shared.u64 t, %1; cvt.u32.u64 %0, t; }" : "=r"(a) : "l"(p));
    return a;
}
__device__ __forceinline__ void cp16(uint32_t saddr, const void* g) {
    asm volatile("cp.async.cg.shared.global [%0], [%1], 16;" :: "r"(saddr), "l"(g));
}
__device__ __forceinline__ void cp_commit() { asm volatile("cp.async.commit_group;" ::: "memory"); }
template <int N>
__device__ __forceinline__ void cp_wait() { asm volatile("cp.async.wait_group %0;" :: "n"(N) : "memory"); }

__device__ __forceinline__ void ldsm_x4(uint32_t& r0, uint32_t& r1, uint32_t& r2, uint32_t& r3,
                                        uint32_t addr) {
    asm volatile("ldmatrix.sync.aligned.m8n8.x4.shared.b16 {%0,%1,%2,%3}, [%4];"
                 : "=r"(r0), "=r"(r1), "=r"(r2), "=r"(r3)
                 : "r"(addr));
}
// fp8 e4m3 MMA, k=32. Fragment layout identical to bf16 m16n8k16 pattern
// with 2 fp8 packed per b16 lane element (so the same ldmatrix.b16 works).
__device__ __forceinline__ void mma16832(float* d, uint32_t a0, uint32_t a1, uint32_t a2,
                                         uint32_t a3, uint32_t b0, uint32_t b1) {
    asm volatile(
        "mma.sync.aligned.m16n8k32.row.col.f32.e4m3.e4m3.f32 "
        "{%0,%1,%2,%3}, {%4,%5,%6,%7}, {%8,%9}, {%0,%1,%2,%3};"
        : "+f"(d[0]), "+f"(d[1]), "+f"(d[2]), "+f"(d[3])
        : "r"(a0), "r"(a1), "r"(a2), "r"(a3), "r"(b0), "r"(b1));
}
// pack four f32 -> e4m3x4 (first PTX source -> high byte)
__device__ __forceinline__ uint32_t pack_e4m3x4(float x0, float x1, float x2, float x3) {
    uint16_t lo, hi;
    asm("cvt.rn.satfinite.e4m3x2.f32 %0, %1, %2;" : "=h"(lo) : "f"(x1), "f"(x0));
    asm("cvt.rn.satfinite.e4m3x2.f32 %0, %1, %2;" : "=h"(hi) : "f"(x3), "f"(x2));
    return (uint32_t)lo | ((uint32_t)hi << 16);
}

// Global symmetric-tile list: rowtiles i<32 own t=0..32 (33 tiles, incl.
// the wrap pair {i,i+32} at t=32), i>=32 own t=0..31.
__device__ __forceinline__ void decode_tile(int idx, int& i, int& t) {
    if (idx < 1056) { i = idx / 33; t = idx - 33 * i; }
    else { int r = idx - 1056; i = 32 + (r >> 5); t = r & 31; }
}

// ======================= kernel A: normalize -> e4m3 (+zero) =====
__global__ void k_normalize(const float* __restrict__ f1, const float* __restrict__ f2,
                            float* __restrict__ out) {
    int row = blockIdx.x;  // 0..8191
    int tid = threadIdx.x;  // 128
    if (tid == 0) g_rowsum[row] = 0.f;  // fold k_zero in here
    if (row == 0 && tid == 1) out[0] = 0.f;
    const float* src = (row < NB) ? (f1 + (size_t)row * NDIM)
                                  : (f2 + (size_t)(row - NB) * NDIM);
    // Each thread owns 4 CONTIGUOUS cols (4t..4t+3) for fp8 byte packing.
    float4 v = *reinterpret_cast<const float4*>(src + tid * 4);
    float ss = v.x * v.x + v.y * v.y + v.z * v.z + v.w * v.w;
#pragma unroll
    for (int o = 16; o > 0; o >>= 1) ss += __shfl_xor_sync(0xFFFFFFFFu, ss, o);
    __shared__ float sred[4];
    if ((tid & 31) == 0) sred[tid >> 5] = ss;
    __syncthreads();
    float tot = sred[0] + sred[1] + sred[2] + sred[3];
    // x16 scale into e4m3 sweet spot (elements ~0.7, max ~3; range 448).
    float scale = 16.f / fmaxf(sqrtf(tot), 1e-12f);
    uint32_t p = pack_e4m3x4(v.x * scale, v.y * scale, v.z * scale, v.w * scale);
    reinterpret_cast<uint32_t*>(g_F8)[(size_t)row * (NDIM / 4) + tid] = p;
}

// ======================= kernel B: exact positive-pair sims ======
__global__ void k_pos(const float* __restrict__ f1, const float* __restrict__ f2) {
    int i = blockIdx.x;  // 0..4095
    int tid = threadIdx.x;  // 128
    const float* a = f1 + (size_t)i * NDIM;
    const float* b = f2 + (size_t)i * NDIM;
    float s11 = 0.f, s22 = 0.f, s12 = 0.f;
#pragma unroll
    for (int c = tid; c < NDIM; c += 128) {
        float x = a[c], y = b[c];
        s11 += x * x; s22 += y * y; s12 += x * y;
    }
#pragma unroll
    for (int o = 16; o > 0; o >>= 1) {
        s11 += __shfl_xor_sync(0xFFFFFFFFu, s11, o);
        s22 += __shfl_xor_sync(0xFFFFFFFFu, s22, o);
        s12 += __shfl_xor_sync(0xFFFFFFFFu, s12, o);
    }
    __shared__ float r11[4], r22[4], r12[4];
    if ((tid & 31) == 0) { r11[tid >> 5] = s11; r22[tid >> 5] = s22; r12[tid >> 5] = s12; }
    __syncthreads();
    if (tid == 0) {
        float t11 = r11[0] + r11[1] + r11[2] + r11[3];
        float t22 = r22[0] + r22[1] + r22[2] + r22[3];
        float t12 = r12[0] + r12[1] + r12[2] + r12[3];
        float inv1 = 1.f / fmaxf(sqrtf(t11), 1e-12f);
        float inv2 = 1.f / fmaxf(sqrtf(t22), 1e-12f);
        g_pos[i] = t12 * inv1 * inv2 * 10.f;  // sim/T
    }
}

// ======================= kernel C: symmetric fused GEMM + exp-sum
// FP8, 512 threads = 16 warps in a 4(M) x 4(N) grid; warp tile 32x32.
// 4 warps/SMSP for latency hiding (R11 lesson: fp8 mma.sync has the same
// MAC rate as bf16 -> the win must come from stall reduction, not fewer
// instructions). 148 CTAs; CTA g owns tiles [g*2080/148,(g+1)*2080/148).
// SMEM: A 128x512 e4m3 pitch 512B swizzled (64 KB); B 3-ring of 128x256
// fp8-k chunks pitch 256B (96 KB).
static constexpr int A_PITCH_B = 512;
static constexpr int B_PITCH_B = 256;
static constexpr int A_BYTES = 128 * A_PITCH_B;             // 65536
static constexpr int B_BUF_BYTES = 128 * B_PITCH_B;         // 32768
static constexpr int SMEM_DYN = A_BYTES + 3 * B_BUF_BYTES;  // 163840

// swizzle: XOR 16B-group index with (row & 7)
__device__ __forceinline__ uint32_t swz(uint32_t row, uint32_t byteoff) {
    return byteoff ^ ((row & 7) << 4);
}

__device__ __forceinline__ void issue_chunk(uint32_t B_base, int tid, int i, int t0, int c) {
    int t = t0 + (c >> 1);
    int n0 = ((i + t) & 63) * 128;
    int kc = c & 1;  // 256 fp8-k per chunk
    uint32_t buf = B_base + (uint32_t)(c % 3) * B_BUF_BYTES;
#pragma unroll
    for (int u = 0; u < 4; u++) {
        int x = tid + u * NTHREADS;
        uint32_t row = (uint32_t)x >> 4, g = (uint32_t)x & 15;
        cp16(buf + row * B_PITCH_B + swz(row, g * 16),
             &g_F8[(size_t)(n0 + (int)row) * NDIM + kc * 256 + (int)g * 16]);
    }
}

__global__ __launch_bounds__(NTHREADS, 1) void k_infonce() {
    extern __shared__ char dyn[];
    uint32_t A_base = smem_u32(dyn);
    uint32_t B_base = A_base + A_BYTES;
    __shared__ float srow[128];

    int tid = threadIdx.x;
    int wid = tid >> 5, lane = tid & 31;
    int warpm = wid >> 2, warpn = wid & 3;  // 4 x 4, warp tile 32x32
    int g = blockIdx.x;
    int s = (g * NTILES_TOTAL) / NCTA;
    int e = ((g + 1) * NTILES_TOTAL) / NCTA;

    // ldmatrix lane addressing (b16 elements = fp8 pairs; swizzled).
    int rowadd = ((lane >> 3) & 1) * 8 + (lane & 7);
    int kadd = (lane >> 4) * 16;
    uint32_t xorm = ((uint32_t)lane & 7) << 4;  // rowadd&7 == lane&7

    uint32_t aRow[2];
#pragma unroll
    for (int mf = 0; mf < 2; mf++)
        aRow[mf] = A_base + (uint32_t)(warpm * 32 + mf * 16 + rowadd) * A_PITCH_B;
    uint32_t bRowRel[2];
#pragma unroll
    for (int nf = 0; nf < 2; nf++)
        bRowRel[nf] = (uint32_t)(warpn * 32 + nf * 16 + rowadd) * B_PITCH_B;

    float acc[2][4][4];              // [mf][q=nf*2+half][j]
    uint32_t af[2][2][4], bf[2][2][4];

    while (s < e) {
        int rowtile, t0;
        decode_tile(s, rowtile, t0);
        int Trow = (rowtile < 32) ? 33 : 32;
        int ntiles = min(e - s, Trow - t0);
        s += ntiles;
        int C = ntiles * 2;  // 256-k chunks
        int m0 = rowtile * 128;
        int grBase = m0 + warpm * 32 + (lane >> 2);
        float accRow[4] = {0.f, 0.f, 0.f, 0.f};

        if (tid < 128) srow[tid] = 0.f;

        // A via cp.async: 64 KB, 4096 16B-groups, swizzled, pitch 512.
#pragma unroll
        for (int u = 0; u < 8; u++) {
            int x = tid + u * NTHREADS;
            uint32_t row = (uint32_t)x >> 5, gg = (uint32_t)x & 31;
            cp16(A_base + row * A_PITCH_B + swz(row, gg * 16),
                 &g_F8[(size_t)(m0 + (int)row) * NDIM + (int)gg * 16]);
        }
        cp_commit();
        issue_chunk(B_base, tid, rowtile, t0, 0);
        cp_commit();
        issue_chunk(B_base, tid, rowtile, t0, 1);
        cp_commit();

        for (int c = 0; c < C; ++c) {
            cp_wait<1>();     // chunk c (and A) complete; chunk c+1 may pend
            __syncthreads();  // visible to all; buf (c-1)%3 free for c+2
            if (c + 2 < C) issue_chunk(B_base, tid, rowtile, t0, c + 2);
            cp_commit();      // one group per iteration (possibly empty)

            int kc = c & 1;
            int t = t0 + (c >> 1);
            int n0 = ((rowtile + t) & 63) * 128;
            if (kc == 0) {
#pragma unroll
                for (int mf = 0; mf < 2; mf++)
#pragma unroll
                    for (int q = 0; q < 4; q++)
#pragma unroll
                        for (int j = 0; j < 4; j++) acc[mf][q][j] = 0.f;
            }

            uint32_t bBuf = B_base + (uint32_t)(c % 3) * B_BUF_BYTES;

            // Fragment double-buffered ks loop (k=32 fp8 = 32B per step).
            {
                uint32_t koffA = (uint32_t)(kc * 256 + kadd) ^ xorm;
                uint32_t koffB = (uint32_t)kadd ^ xorm;
#pragma unroll
                for (int mf = 0; mf < 2; mf++)
                    ldsm_x4(af[0][mf][0], af[0][mf][1], af[0][mf][2], af[0][mf][3],
                            aRow[mf] + koffA);
#pragma unroll
                for (int nf = 0; nf < 2; nf++)
                    ldsm_x4(bf[0][nf][0], bf[0][nf][1], bf[0][nf][2], bf[0][nf][3],
                            bBuf + bRowRel[nf] + koffB);
            }
#pragma unroll
            for (int ks = 0; ks < 8; ++ks) {
                int cur = ks & 1, nxt = cur ^ 1;
                if (ks < 7) {
                    uint32_t koffA = (uint32_t)(kc * 256 + (ks + 1) * 32 + kadd) ^ xorm;
                    uint32_t koffB = (uint32_t)((ks + 1) * 32 + kadd) ^ xorm;
#pragma unroll
                    for (int mf = 0; mf < 2; mf++)
                        ldsm_x4(af[nxt][mf][0], af[nxt][mf][1], af[nxt][mf][2], af[nxt][mf][3],
                                aRow[mf] + koffA);
#pragma unroll
                    for (int nf = 0; nf < 2; nf++)
                        ldsm_x4(bf[nxt][nf][0], bf[nxt][nf][1], bf[nxt][nf][2], bf[nxt][nf][3],
                                bBuf + bRowRel[nf] + koffB);
                }
#pragma unroll
                for (int nf = 0; nf < 2; nf++) {
#pragma unroll
                    for (int mf = 0; mf < 2; mf++) {
                        mma16832(acc[mf][nf * 2 + 0], af[cur][mf][0], af[cur][mf][1],
                                 af[cur][mf][2], af[cur][mf][3], bf[cur][nf][0], bf[cur][nf][2]);
                        mma16832(acc[mf][nf * 2 + 1], af[cur][mf][0], af[cur][mf][1],
                                 af[cur][mf][2], af[cur][mf][3], bf[cur][nf][1], bf[cur][nf][3]);
                    }
                }
            }

            if (kc != 1) continue;

            // ---------------- per-tile epilogue ----------------
            if (t == 0) {
                // Diagonal tile: row sums only, self-similarity masked.
#pragma unroll
                for (int mf = 0; mf < 2; mf++) {
                    int gr0 = grBase + mf * 16;
#pragma unroll
                    for (int q = 0; q < 4; q++) {
                        int c0 = n0 + warpn * 32 + (q >> 1) * 16 + (q & 1) * 8 + 2 * (lane & 3);
#pragma unroll
                        for (int j = 0; j < 4; j++) {
                            float arg = fmaf(acc[mf][q][j], EX2_A, EX2_B);
                            float ev;
                            asm("ex2.approx.ftz.f32 %0, %1;" : "=f"(ev) : "f"(arg));
                            int gc = c0 + (j & 1);
                            int gr = gr0 + (j >> 1) * 8;
                            if (gc != gr) accRow[mf * 2 + (j >> 1)] += ev;
                        }
                    }
                }
            } else {
                // Off-diagonal tile: rows (tile i) + columns (tile j).
                float colAcc[8];
#pragma unroll
                for (int x = 0; x < 8; x++) colAcc[x] = 0.f;
#pragma unroll
                for (int mf = 0; mf < 2; mf++) {
#pragma unroll
                    for (int q = 0; q < 4; q++) {
#pragma unroll
                        for (int j = 0; j < 4; j++) {
                            float arg = fmaf(acc[mf][q][j], EX2_A, EX2_B);
                            float ev;
                            asm("ex2.approx.ftz.f32 %0, %1;" : "=f"(ev) : "f"(arg));
                            accRow[mf * 2 + (j >> 1)] += ev;
                            colAcc[q * 2 + (j & 1)] += ev;
                        }
                    }
                }
#pragma unroll
                for (int x = 0; x < 8; x++) {
                    float v = colAcc[x];
                    v += __shfl_xor_sync(0xFFFFFFFFu, v, 4);
                    v += __shfl_xor_sync(0xFFFFFFFFu, v, 8);
                    v += __shfl_xor_sync(0xFFFFFFFFu, v, 16);
                    if (lane < 4) {
                        int q = x >> 1, jlo = x & 1;
                        int col = n0 + warpn * 32 + (q >> 1) * 16 + (q & 1) * 8 + 2 * lane + jlo;
                        atomicAdd(&g_rowsum[col], v);
                    }
                }
            }
        }

        // Segment row flush (also the drain barrier before next A reload).
        __syncthreads();
#pragma unroll
        for (int x = 0; x < 4; x++) {
            float v = accRow[x];
            v += __shfl_xor_sync(0xFFFFFFFFu, v, 1);
            v += __shfl_xor_sync(0xFFFFFFFFu, v, 2);
            if ((lane & 3) == 0)
                atomicAdd(&srow[warpm * 32 + x * 8 + (lane >> 2)], v);
        }
        __syncthreads();
        if (tid < 128)
            atomicAdd(&g_rowsum[m0 + tid], srow[tid]);
    }
}

// ======================= kernel D: final reduction ===============
__global__ void k_finish(float* __restrict__ out) {
    int tid = threadIdx.x;  // 256, grid 32
    int r = blockIdx.x * 256 + tid;
    // LSE_r = 10 + log(sum exp(sim-10));  loss_r = LSE_r - pos-pair sim
    float acc = 10.f + __logf(g_rowsum[r]) - g_pos[r & (NB - 1)];
#pragma unroll
    for (int o = 16; o > 0; o >>= 1) acc += __shfl_xor_sync(0xFFFFFFFFu, acc, o);
    __shared__ float sred[8];
    if ((tid & 31) == 0) sred[tid >> 5] = acc;
    __syncthreads();
    if (tid == 0) {
        float s = 0.f;
#pragma unroll
        for (int i = 0; i < 8; i++) s += sred[i];
        atomicAdd(out, s * (1.f / (float)NROWS));
    }
}

// ======================= launch ==================================
extern "C" void kernel_launch(void* const* d_in, const int* in_sizes, int n_in,
                              void* d_out, int out_size) {
    const float* f1 = (const float*)d_in[0];
    const float* f2 = (const float*)d_in[1];
    float* out = (float*)d_out;

    cudaFuncSetAttribute(k_infonce, cudaFuncAttributeMaxDynamicSharedMemorySize, SMEM_DYN);

    k_normalize<<<NROWS, 128>>>(f1, f2, out);
    k_pos<<<NB, 128>>>(f1, f2);
    k_infonce<<<NCTA, NTHREADS, SMEM_DYN>>>();
    k_finish<<<32, 256>>>(out);
}